// round 1
// baseline (speedup 1.0000x reference)
#include <cuda_runtime.h>
#include <math.h>

// ---------------------------------------------------------------------------
// Problem constants
// ---------------------------------------------------------------------------
#define BB    256      // batch
#define LSEQ  256      // sequence length
#define VV    14       // vocab
#define EMBD  512      // embedding dim
#define HH    128      // L/2 after maxpool
#define CO    256      // conv output channels (both big branches)
#define KDIM  1536     // 512 * 3 taps
#define NSPLIT 32      // split-K factor for linear GEMM

// ---------------------------------------------------------------------------
// Device scratch (static allocation: harness forbids runtime allocs)
// ---------------------------------------------------------------------------
__device__ __align__(128) float g_pooled[BB * 130 * EMBD];   // padded [b][h+1][c], rows 0 & 129 zero
__device__ __align__(128) float g_Wc[KDIM * CO];             // repacked conv weights [k][o]
__device__ __align__(128) float g_convT[BB * CO * HH];       // conv out, [b][o][h] (matches flatten order)
__device__ __align__(128) float g_part[NSPLIT * BB * 128];   // split-K partials
__device__ __align__(128) float g_f[BB * 128];               // linear output
__device__ __align__(128) float g_eout[BB * 128];            // enemy softmax
__device__ __align__(128) float g_Lmid[64 * 256];            // column sums of manip_lin_w middle rows
__device__ __align__(128) int   g_tokens[BB * LSEQ];         // manipulator tokens

// ---------------------------------------------------------------------------
// 1. Embedding gather + maxpool(2) -> padded [B,130,512] layout
// ---------------------------------------------------------------------------
__global__ void pool_kernel(const int* __restrict__ tok, const float* __restrict__ emb)
{
    int idx = blockIdx.x * blockDim.x + threadIdx.x;   // < BB*130*EMBD
    int c  = idx & (EMBD - 1);
    int r  = idx >> 9;
    int hp = r % 130;
    int b  = r / 130;
    float v = 0.0f;
    if (hp >= 1 && hp <= HH) {
        int h  = hp - 1;
        int t0 = tok[b * LSEQ + 2 * h];
        int t1 = tok[b * LSEQ + 2 * h + 1];
        v = fmaxf(emb[t0 * EMBD + c], emb[t1 * EMBD + c]);
    }
    g_pooled[idx] = v;
}

// ---------------------------------------------------------------------------
// 2. Repack conv weights: Wc[(tap*512+i)*256 + o] = cw[o][i][tap][1]
//    (only middle kernel column matters: W-dim is 1 with pad 1)
// ---------------------------------------------------------------------------
__global__ void repack_kernel(const float* __restrict__ cw)
{
    int idx = blockIdx.x * blockDim.x + threadIdx.x;   // < KDIM*CO
    int o   = idx & 255;
    int k   = idx >> 8;
    int tap = k >> 9;
    int i   = k & 511;
    g_Wc[idx] = cw[o * 4608 + i * 9 + tap * 3 + 1];
}

// ---------------------------------------------------------------------------
// 3. Conv-as-GEMM: M=32768 (b,h), N=256 (o), K=1536.
//    A row (b,h) = &g_pooled[(b*130 + h)*512], contiguous 1536 floats (im2col free).
//    Output written transposed: convT[b][o*128+h]  (== flatten order o*128+h).
// ---------------------------------------------------------------------------
__global__ void __launch_bounds__(256) gemm_conv(const float* __restrict__ cb)
{
    __shared__ float As[16][128];
    __shared__ float Bs[16][128];
    float acc[8][8];
#pragma unroll
    for (int i = 0; i < 8; i++)
#pragma unroll
        for (int j = 0; j < 8; j++) acc[i][j] = 0.0f;

    int t  = threadIdx.x;
    int tx = t & 15, ty = t >> 4;
    int bx = blockIdx.x;            // batch index == M tile (128 rows = one b)
    int by = blockIdx.y;            // N tile (0..1)

    const float* Abase = g_pooled + (size_t)bx * (130 * EMBD);
    int aRow = t >> 1;              // 0..127  (h)
    int aCol = (t & 1) * 8;         // 0 or 8
    int bRow = t >> 4;              // 0..15   (kk)
    int bCol = (t & 15) * 8;

    for (int k0 = 0; k0 < KDIM; k0 += 16) {
        const float* ap = Abase + aRow * EMBD + k0 + aCol;
        float4 a0 = *(const float4*)ap;
        float4 a1 = *(const float4*)(ap + 4);
        As[aCol + 0][aRow] = a0.x; As[aCol + 1][aRow] = a0.y;
        As[aCol + 2][aRow] = a0.z; As[aCol + 3][aRow] = a0.w;
        As[aCol + 4][aRow] = a1.x; As[aCol + 5][aRow] = a1.y;
        As[aCol + 6][aRow] = a1.z; As[aCol + 7][aRow] = a1.w;

        const float* bp = g_Wc + (size_t)(k0 + bRow) * CO + by * 128 + bCol;
        *(float4*)&Bs[bRow][bCol]     = *(const float4*)bp;
        *(float4*)&Bs[bRow][bCol + 4] = *(const float4*)(bp + 4);
        __syncthreads();

#pragma unroll
        for (int kk = 0; kk < 16; kk++) {
            float ra[8], rb[8];
            *(float4*)(ra)     = *(const float4*)&As[kk][ty * 8];
            *(float4*)(ra + 4) = *(const float4*)&As[kk][ty * 8 + 4];
            *(float4*)(rb)     = *(const float4*)&Bs[kk][tx * 8];
            *(float4*)(rb + 4) = *(const float4*)&Bs[kk][tx * 8 + 4];
#pragma unroll
            for (int i = 0; i < 8; i++)
#pragma unroll
                for (int j = 0; j < 8; j++)
                    acc[i][j] += ra[i] * rb[j];
        }
        __syncthreads();
    }

    float* cbase = g_convT + (size_t)bx * (CO * HH);
#pragma unroll
    for (int j = 0; j < 8; j++) {
        int o = by * 128 + tx * 8 + j;
        float bias = cb[o];
        float4 v0 = make_float4(acc[0][j] + bias, acc[1][j] + bias,
                                acc[2][j] + bias, acc[3][j] + bias);
        float4 v1 = make_float4(acc[4][j] + bias, acc[5][j] + bias,
                                acc[6][j] + bias, acc[7][j] + bias);
        *(float4*)&cbase[o * HH + ty * 8]     = v0;
        *(float4*)&cbase[o * HH + ty * 8 + 4] = v1;
    }
}

// ---------------------------------------------------------------------------
// 4. Linear GEMM split-K: f = convT [256,32768] @ lw [32768,128]
//    grid (4 Mtiles x 32 Ksplits); deterministic fixed-order reduce afterwards.
// ---------------------------------------------------------------------------
__global__ void __launch_bounds__(256) gemm_lin(const float* __restrict__ lw)
{
    __shared__ float As[16][64];
    __shared__ float Bs[16][128];
    float acc[4][8];
#pragma unroll
    for (int i = 0; i < 4; i++)
#pragma unroll
        for (int j = 0; j < 8; j++) acc[i][j] = 0.0f;

    int t  = threadIdx.x;
    int tx = t & 15, ty = t >> 4;
    int m0    = blockIdx.x * 64;
    int kbase = blockIdx.y * 1024;

    int aRow = t >> 2;            // 0..63
    int aCol = (t & 3) * 4;       // 0,4,8,12
    int bRow = t >> 4;            // 0..15
    int bCol = (t & 15) * 8;

    for (int k0 = 0; k0 < 1024; k0 += 16) {
        float4 a = *(const float4*)(g_convT + (size_t)(m0 + aRow) * 32768 + kbase + k0 + aCol);
        As[aCol + 0][aRow] = a.x; As[aCol + 1][aRow] = a.y;
        As[aCol + 2][aRow] = a.z; As[aCol + 3][aRow] = a.w;

        const float* bp = lw + (size_t)(kbase + k0 + bRow) * 128 + bCol;
        *(float4*)&Bs[bRow][bCol]     = *(const float4*)bp;
        *(float4*)&Bs[bRow][bCol + 4] = *(const float4*)(bp + 4);
        __syncthreads();

#pragma unroll
        for (int kk = 0; kk < 16; kk++) {
            float ra[4], rb[8];
            *(float4*)ra       = *(const float4*)&As[kk][ty * 4];
            *(float4*)(rb)     = *(const float4*)&Bs[kk][tx * 8];
            *(float4*)(rb + 4) = *(const float4*)&Bs[kk][tx * 8 + 4];
#pragma unroll
            for (int i = 0; i < 4; i++)
#pragma unroll
                for (int j = 0; j < 8; j++)
                    acc[i][j] += ra[i] * rb[j];
        }
        __syncthreads();
    }

    float* pbase = g_part + (size_t)blockIdx.y * (BB * 128);
#pragma unroll
    for (int i = 0; i < 4; i++) {
        int m = m0 + ty * 4 + i;
        *(float4*)&pbase[m * 128 + tx * 8]     = *(float4*)&acc[i][0];
        *(float4*)&pbase[m * 128 + tx * 8 + 4] = *(float4*)&acc[i][4];
    }
}

// Fixed-order split-K reduction + bias
__global__ void reduce_kernel(const float* __restrict__ bias)
{
    int idx = blockIdx.x * 256 + threadIdx.x;   // < 32768
    float s = 0.0f;
#pragma unroll
    for (int ks = 0; ks < NSPLIT; ks++)
        s += g_part[(size_t)ks * (BB * 128) + idx];
    g_f[idx] = s + bias[idx & 127];
}

// ---------------------------------------------------------------------------
// 5. Softmax over 128 (enemy branch)
// ---------------------------------------------------------------------------
__global__ void softmax128_kernel()
{
    __shared__ float s[128];
    int b = blockIdx.x, t = threadIdx.x;
    float v = g_f[b * 128 + t];
    s[t] = v; __syncthreads();
    for (int o = 64; o > 0; o >>= 1) { if (t < o) s[t] = fmaxf(s[t], s[t + o]); __syncthreads(); }
    float mx = s[0]; __syncthreads();
    float e = expf(v - mx);
    s[t] = e; __syncthreads();
    for (int o = 64; o > 0; o >>= 1) { if (t < o) s[t] += s[t + o]; __syncthreads(); }
    g_eout[b * 128 + t] = e / s[0];
}

// ---------------------------------------------------------------------------
// 6. Precompute Lmid[o][j] = sum_{h=1..126} manip_lin_w[o*128+h][j]
// ---------------------------------------------------------------------------
__global__ void lmid_kernel(const float* __restrict__ mlw)
{
    int idx = blockIdx.x * 256 + threadIdx.x;   // < 64*256
    int o = idx >> 8, j = idx & 255;
    float s = 0.0f;
    for (int h = 1; h <= 126; h++)
        s += mlw[(size_t)(o * 128 + h) * 256 + j];
    g_Lmid[idx] = s;
}

// ---------------------------------------------------------------------------
// 7. Manipulator + token quantization.
//    Conv input is constant over H (broadcast), W=1 => only 3 distinct conv
//    outputs per (b,o): top (taps 1,2), mid (taps 0,1,2), bot (taps 0,1).
//    perm == arange(B) (greedy loop is deterministic identity), so no gather.
// ---------------------------------------------------------------------------
__global__ void manip_kernel(const float* __restrict__ mcw, const float* __restrict__ mcb,
                             const float* __restrict__ mlw, const float* __restrict__ mlb)
{
    __shared__ float eo[128];
    __shared__ float r[192];
    int b = blockIdx.x, t = threadIdx.x;
    if (t < 128) eo[t] = g_eout[b * 128 + t];
    __syncthreads();
    if (t < 192) {
        int g = t / 64, o = t % 64;
        float acc = mcb[o];
        for (int i = 0; i < 128; i++) {
            const float* wp = mcw + o * 1152 + i * 9;   // [64][128][3][3], kw=1
            float w0 = wp[1], w1 = wp[4], w2 = wp[7];
            float ws = (g == 0) ? (w1 + w2) : ((g == 1) ? (w0 + w1 + w2) : (w0 + w1));
            acc += eo[i] * ws;
        }
        r[t] = fmaxf(acc, 0.0f);                        // ReLU (bias inside)
    }
    __syncthreads();
    // m[b][t] over flattened (o,h) with h-groups collapsed
    float mm = mlb[t];
    for (int o = 0; o < 64; o++) {
        mm += r[o]       * mlw[(size_t)(o * 128) * 256 + t];        // h = 0
        mm += r[64 + o]  * g_Lmid[o * 256 + t];                     // h = 1..126
        mm += r[128 + o] * mlw[(size_t)(o * 128 + 127) * 256 + t];  // h = 127
    }
    g_tokens[b * 256 + t] = (int)(fmodf(floorf(fabsf(mm) * 100.0f), 14.0f));
}

// ---------------------------------------------------------------------------
// 8. Final: f @ lin2[128,14] + b2 -> softmax(14) -> out
// ---------------------------------------------------------------------------
__global__ void final_kernel(const float* __restrict__ w2, const float* __restrict__ b2,
                             float* __restrict__ out)
{
    __shared__ float fr[128];
    __shared__ float lg[14];
    int b = blockIdx.x, t = threadIdx.x;   // 32 threads
    for (int i = t; i < 128; i += 32) fr[i] = g_f[b * 128 + i];
    __syncthreads();
    if (t < 14) {
        float acc = b2[t];
        for (int j = 0; j < 128; j++) acc += fr[j] * w2[j * 14 + t];
        lg[t] = acc;
    }
    __syncthreads();
    if (t == 0) {
        float mx = lg[0];
        for (int v = 1; v < 14; v++) mx = fmaxf(mx, lg[v]);
        float s = 0.0f;
        for (int v = 0; v < 14; v++) { float e = expf(lg[v] - mx); lg[v] = e; s += e; }
        float inv = 1.0f / s;
        for (int v = 0; v < 14; v++) out[b * 14 + v] = lg[v] * inv;
    }
}

// ---------------------------------------------------------------------------
// Launch
// ---------------------------------------------------------------------------
extern "C" void kernel_launch(void* const* d_in, const int* in_sizes, int n_in,
                              void* d_out, int out_size)
{
    const int*   x       = (const int*)  d_in[0];
    const float* e_emb   = (const float*)d_in[1];
    const float* e_cw    = (const float*)d_in[2];
    const float* e_cb    = (const float*)d_in[3];
    const float* e_lw    = (const float*)d_in[4];
    const float* e_lb    = (const float*)d_in[5];
    // d_in[6] = rand_proj  (dead: fog_of_war is provably the identity permutation)
    const float* m_cw    = (const float*)d_in[7];
    const float* m_cb    = (const float*)d_in[8];
    const float* m_lw    = (const float*)d_in[9];
    const float* m_lb    = (const float*)d_in[10];
    const float* f_emb   = (const float*)d_in[11];
    const float* f_cw    = (const float*)d_in[12];
    const float* f_cb    = (const float*)d_in[13];
    const float* f_lw    = (const float*)d_in[14];
    const float* f_lb    = (const float*)d_in[15];
    const float* f_l2w   = (const float*)d_in[16];
    const float* f_l2b   = (const float*)d_in[17];
    float* out = (float*)d_out;

    const int poolThreads = BB * 130 * EMBD;        // 17,039,360
    const int repackThreads = KDIM * CO;            // 393,216

    // ---- enemy branch ----
    pool_kernel   <<<poolThreads / 256, 256>>>(x, e_emb);
    repack_kernel <<<repackThreads / 256, 256>>>(e_cw);
    gemm_conv     <<<dim3(BB, 2), 256>>>(e_cb);
    gemm_lin      <<<dim3(4, NSPLIT), 256>>>(e_lw);
    reduce_kernel <<<(BB * 128) / 256, 256>>>(e_lb);
    softmax128_kernel<<<BB, 128>>>();

    // ---- manipulator + tokens ----
    lmid_kernel   <<<(64 * 256) / 256, 256>>>(m_lw);
    manip_kernel  <<<BB, 256>>>(m_cw, m_cb, m_lw, m_lb);

    // ---- friend branch ----
    int* tok_dev;
    cudaGetSymbolAddress((void**)&tok_dev, g_tokens);   // host-side, capture-safe (no alloc)
    pool_kernel   <<<poolThreads / 256, 256>>>(tok_dev, f_emb);
    repack_kernel <<<repackThreads / 256, 256>>>(f_cw);
    gemm_conv     <<<dim3(BB, 2), 256>>>(f_cb);
    gemm_lin      <<<dim3(4, NSPLIT), 256>>>(f_lw);
    reduce_kernel <<<(BB * 128) / 256, 256>>>(f_lb);
    final_kernel  <<<BB, 32>>>(f_l2w, f_l2b, out);
}

// round 2
// speedup vs baseline: 1.4643x; 1.4643x over previous
#include <cuda_runtime.h>
#include <math.h>
#include <stdint.h>

// ---------------------------------------------------------------------------
// Problem constants
// ---------------------------------------------------------------------------
#define BB    256      // batch
#define LSEQ  256      // sequence length
#define VV    14       // vocab
#define EMBD  512      // embedding dim
#define HH    128      // L/2 after maxpool
#define CO    256      // conv output channels
#define KDIM  1536     // 512 * 3 taps
#define NSPLIT 64      // split-K factor for linear GEMM

// ---------------------------------------------------------------------------
// Device scratch (static allocation: harness forbids runtime allocs)
// ---------------------------------------------------------------------------
__device__ __align__(128) float g_pooled[BB * 130 * EMBD];   // padded [b][h+1][c], rows 0 & 129 zero
__device__ __align__(128) float g_Wc[KDIM * CO];             // repacked conv weights [k][o]
__device__ __align__(128) float g_convT[BB * CO * HH];       // conv out, [b][o][h] (flatten order)
__device__ __align__(128) float g_part[NSPLIT * BB * 128];   // split-K partials
__device__ __align__(128) float g_f[BB * 128];               // linear output
__device__ __align__(128) float g_eout[BB * 128];            // enemy softmax
__device__ __align__(128) float g_Lmid[64 * 256];            // column sums of manip_lin_w middle rows
__device__ __align__(128) int   g_tokens[BB * LSEQ];         // manipulator tokens

// ---------------------------------------------------------------------------
// MMA helpers (tf32 m16n8k8, row.col)
// ---------------------------------------------------------------------------
__device__ __forceinline__ uint32_t f2tf32(float x) {
    uint32_t r;
    asm("cvt.rna.tf32.f32 %0, %1;" : "=r"(r) : "f"(x));
    return r;
}

__device__ __forceinline__ void mma8(float* c, const uint32_t* a, const uint32_t* b) {
    asm volatile(
        "mma.sync.aligned.m16n8k8.row.col.f32.tf32.tf32.f32 "
        "{%0,%1,%2,%3}, {%4,%5,%6,%7}, {%8,%9}, {%0,%1,%2,%3};"
        : "+f"(c[0]), "+f"(c[1]), "+f"(c[2]), "+f"(c[3])
        : "r"(a[0]), "r"(a[1]), "r"(a[2]), "r"(a[3]), "r"(b[0]), "r"(b[1]));
}

// ---------------------------------------------------------------------------
// 1. Embedding gather + maxpool(2) -> padded [B,130,512] layout
// ---------------------------------------------------------------------------
__global__ void pool_kernel(const int* __restrict__ tok, const float* __restrict__ emb)
{
    int idx = blockIdx.x * blockDim.x + threadIdx.x;
    int c  = idx & (EMBD - 1);
    int r  = idx >> 9;
    int hp = r % 130;
    int b  = r / 130;
    float v = 0.0f;
    if (hp >= 1 && hp <= HH) {
        int h  = hp - 1;
        int t0 = tok[b * LSEQ + 2 * h];
        int t1 = tok[b * LSEQ + 2 * h + 1];
        v = fmaxf(emb[t0 * EMBD + c], emb[t1 * EMBD + c]);
    }
    g_pooled[idx] = v;
}

// ---------------------------------------------------------------------------
// 2. Repack conv weights: Wc[(tap*512+i)*256 + o] = cw[o][i][tap][1]
// ---------------------------------------------------------------------------
__global__ void repack_kernel(const float* __restrict__ cw)
{
    int idx = blockIdx.x * blockDim.x + threadIdx.x;
    int o   = idx & 255;
    int k   = idx >> 8;
    int tap = k >> 9;
    int i   = k & 511;
    g_Wc[idx] = cw[o * 4608 + i * 9 + tap * 3 + 1];
}

// ---------------------------------------------------------------------------
// 3. Conv-as-GEMM (tensor cores): per block M=128 (one batch's 128 h rows),
//    N=128 tile, K=1536. HIPREC -> 3xTF32 (hi/lo split, fp32-level accuracy).
//    A rows are contiguous 1536-float windows of g_pooled (im2col free).
// ---------------------------------------------------------------------------
template<bool HIPREC>
__global__ void __launch_bounds__(256) gemm_conv_mma(const float* __restrict__ cb)
{
    const int PL = HIPREC ? 2 : 1;
    __shared__ uint32_t As[HIPREC ? 2 : 1][16][136];
    __shared__ uint32_t Bs[HIPREC ? 2 : 1][16][136];

    float acc[2][8][4];
#pragma unroll
    for (int i = 0; i < 2; i++)
#pragma unroll
        for (int j = 0; j < 8; j++)
#pragma unroll
            for (int q = 0; q < 4; q++) acc[i][j][q] = 0.0f;

    int t    = threadIdx.x;
    int lane = t & 31;
    int wid  = t >> 5;
    int wm   = wid & 3;            // warp M tile: 32 rows at wm*32
    int wn   = wid >> 2;           // warp N tile: 64 cols at wn*64
    int gid  = lane >> 2;
    int tig  = lane & 3;

    int bx = blockIdx.x;           // batch index
    int by = blockIdx.y;           // N tile (0..1)

    const float* Abase = g_pooled + (size_t)bx * (130 * EMBD);
    int aRow = t >> 1;             // 0..127 (h)
    int aCol = (t & 1) * 8;
    int bRow = t >> 4;             // 0..15
    int bCol = (t & 15) * 8;

    for (int k0 = 0; k0 < KDIM; k0 += 16) {
        const float* ap = Abase + aRow * EMBD + k0 + aCol;
        float4 a0 = *(const float4*)ap;
        float4 a1 = *(const float4*)(ap + 4);
        float av[8] = {a0.x, a0.y, a0.z, a0.w, a1.x, a1.y, a1.z, a1.w};
#pragma unroll
        for (int j = 0; j < 8; j++) {
            uint32_t hi = f2tf32(av[j]);
            As[0][aCol + j][aRow] = hi;
            if (HIPREC) {
                float lo = av[j] - __uint_as_float(hi);
                As[1][aCol + j][aRow] = f2tf32(lo);
            }
        }
        const float* bp = g_Wc + (size_t)(k0 + bRow) * CO + by * 128 + bCol;
        float4 b0 = *(const float4*)bp;
        float4 b1 = *(const float4*)(bp + 4);
        float bv[8] = {b0.x, b0.y, b0.z, b0.w, b1.x, b1.y, b1.z, b1.w};
#pragma unroll
        for (int j = 0; j < 8; j++) {
            uint32_t hi = f2tf32(bv[j]);
            Bs[0][bRow][bCol + j] = hi;
            if (HIPREC) {
                float lo = bv[j] - __uint_as_float(hi);
                Bs[1][bRow][bCol + j] = f2tf32(lo);
            }
        }
        __syncthreads();

#pragma unroll
        for (int ks = 0; ks < 2; ks++) {
            int kr = ks * 8;
            uint32_t af[HIPREC ? 2 : 1][2][4];
#pragma unroll
            for (int p = 0; p < PL; p++)
#pragma unroll
                for (int mi = 0; mi < 2; mi++) {
                    int m = wm * 32 + mi * 16;
                    af[p][mi][0] = As[p][kr + tig][m + gid];
                    af[p][mi][1] = As[p][kr + tig][m + gid + 8];
                    af[p][mi][2] = As[p][kr + tig + 4][m + gid];
                    af[p][mi][3] = As[p][kr + tig + 4][m + gid + 8];
                }
#pragma unroll
            for (int nj = 0; nj < 8; nj++) {
                int n = wn * 64 + nj * 8;
                uint32_t bf[HIPREC ? 2 : 1][2];
#pragma unroll
                for (int p = 0; p < PL; p++) {
                    bf[p][0] = Bs[p][kr + tig][n + gid];
                    bf[p][1] = Bs[p][kr + tig + 4][n + gid];
                }
#pragma unroll
                for (int mi = 0; mi < 2; mi++) {
                    mma8(acc[mi][nj], af[0][mi], bf[0]);
                    if (HIPREC) {
                        mma8(acc[mi][nj], af[0][mi], bf[1]);
                        mma8(acc[mi][nj], af[1][mi], bf[0]);
                    }
                }
            }
        }
        __syncthreads();
    }

    // Epilogue: convT[b][o*128 + h]
    float* cbase = g_convT + (size_t)bx * (CO * HH);
#pragma unroll
    for (int mi = 0; mi < 2; mi++) {
        int h0 = wm * 32 + mi * 16 + gid;
#pragma unroll
        for (int nj = 0; nj < 8; nj++) {
            int o0 = by * 128 + wn * 64 + nj * 8 + 2 * tig;
            float bv0 = cb[o0], bv1 = cb[o0 + 1];
            cbase[(size_t)o0 * HH + h0]           = acc[mi][nj][0] + bv0;
            cbase[(size_t)(o0 + 1) * HH + h0]     = acc[mi][nj][1] + bv1;
            cbase[(size_t)o0 * HH + h0 + 8]       = acc[mi][nj][2] + bv0;
            cbase[(size_t)(o0 + 1) * HH + h0 + 8] = acc[mi][nj][3] + bv1;
        }
    }
}

// ---------------------------------------------------------------------------
// 4. Linear GEMM (tensor cores, split-K): f = convT[256,32768] @ lw[32768,128]
//    grid (2 Mtiles x NSPLIT Ksplits), K chunk = 512. Fixed-order reduce after.
// ---------------------------------------------------------------------------
template<bool HIPREC>
__global__ void __launch_bounds__(256) gemm_lin_mma(const float* __restrict__ lw)
{
    const int PL = HIPREC ? 2 : 1;
    __shared__ uint32_t As[HIPREC ? 2 : 1][16][136];
    __shared__ uint32_t Bs[HIPREC ? 2 : 1][16][136];

    float acc[2][8][4];
#pragma unroll
    for (int i = 0; i < 2; i++)
#pragma unroll
        for (int j = 0; j < 8; j++)
#pragma unroll
            for (int q = 0; q < 4; q++) acc[i][j][q] = 0.0f;

    int t    = threadIdx.x;
    int lane = t & 31;
    int wid  = t >> 5;
    int wm   = wid & 3;
    int wn   = wid >> 2;
    int gid  = lane >> 2;
    int tig  = lane & 3;

    int m0    = blockIdx.x * 128;
    int kbase = blockIdx.y * (32768 / NSPLIT);   // 512-wide chunk

    int aRow = t >> 1;
    int aCol = (t & 1) * 8;
    int bRow = t >> 4;
    int bCol = (t & 15) * 8;

    for (int k0 = 0; k0 < 32768 / NSPLIT; k0 += 16) {
        const float* ap = g_convT + (size_t)(m0 + aRow) * 32768 + kbase + k0 + aCol;
        float4 a0 = *(const float4*)ap;
        float4 a1 = *(const float4*)(ap + 4);
        float av[8] = {a0.x, a0.y, a0.z, a0.w, a1.x, a1.y, a1.z, a1.w};
#pragma unroll
        for (int j = 0; j < 8; j++) {
            uint32_t hi = f2tf32(av[j]);
            As[0][aCol + j][aRow] = hi;
            if (HIPREC) {
                float lo = av[j] - __uint_as_float(hi);
                As[1][aCol + j][aRow] = f2tf32(lo);
            }
        }
        const float* bp = lw + (size_t)(kbase + k0 + bRow) * 128 + bCol;
        float4 b0 = *(const float4*)bp;
        float4 b1 = *(const float4*)(bp + 4);
        float bv[8] = {b0.x, b0.y, b0.z, b0.w, b1.x, b1.y, b1.z, b1.w};
#pragma unroll
        for (int j = 0; j < 8; j++) {
            uint32_t hi = f2tf32(bv[j]);
            Bs[0][bRow][bCol + j] = hi;
            if (HIPREC) {
                float lo = bv[j] - __uint_as_float(hi);
                Bs[1][bRow][bCol + j] = f2tf32(lo);
            }
        }
        __syncthreads();

#pragma unroll
        for (int ks = 0; ks < 2; ks++) {
            int kr = ks * 8;
            uint32_t af[HIPREC ? 2 : 1][2][4];
#pragma unroll
            for (int p = 0; p < PL; p++)
#pragma unroll
                for (int mi = 0; mi < 2; mi++) {
                    int m = wm * 32 + mi * 16;
                    af[p][mi][0] = As[p][kr + tig][m + gid];
                    af[p][mi][1] = As[p][kr + tig][m + gid + 8];
                    af[p][mi][2] = As[p][kr + tig + 4][m + gid];
                    af[p][mi][3] = As[p][kr + tig + 4][m + gid + 8];
                }
#pragma unroll
            for (int nj = 0; nj < 8; nj++) {
                int n = wn * 64 + nj * 8;
                uint32_t bf[HIPREC ? 2 : 1][2];
#pragma unroll
                for (int p = 0; p < PL; p++) {
                    bf[p][0] = Bs[p][kr + tig][n + gid];
                    bf[p][1] = Bs[p][kr + tig + 4][n + gid];
                }
#pragma unroll
                for (int mi = 0; mi < 2; mi++) {
                    mma8(acc[mi][nj], af[0][mi], bf[0]);
                    if (HIPREC) {
                        mma8(acc[mi][nj], af[0][mi], bf[1]);
                        mma8(acc[mi][nj], af[1][mi], bf[0]);
                    }
                }
            }
        }
        __syncthreads();
    }

    float* pbase = g_part + (size_t)blockIdx.y * (BB * 128);
#pragma unroll
    for (int mi = 0; mi < 2; mi++) {
        int m = m0 + wm * 32 + mi * 16 + gid;
#pragma unroll
        for (int nj = 0; nj < 8; nj++) {
            int n = wn * 64 + nj * 8 + 2 * tig;
            pbase[(size_t)m * 128 + n]           = acc[mi][nj][0];
            pbase[(size_t)m * 128 + n + 1]       = acc[mi][nj][1];
            pbase[(size_t)(m + 8) * 128 + n]     = acc[mi][nj][2];
            pbase[(size_t)(m + 8) * 128 + n + 1] = acc[mi][nj][3];
        }
    }
}

// Fixed-order split-K reduction + bias
__global__ void reduce_kernel(const float* __restrict__ bias)
{
    int idx = blockIdx.x * 256 + threadIdx.x;   // < 32768
    float s = 0.0f;
#pragma unroll
    for (int ks = 0; ks < NSPLIT; ks++)
        s += g_part[(size_t)ks * (BB * 128) + idx];
    g_f[idx] = s + bias[idx & 127];
}

// ---------------------------------------------------------------------------
// 5. Softmax over 128 (enemy branch)
// ---------------------------------------------------------------------------
__global__ void softmax128_kernel()
{
    __shared__ float s[128];
    int b = blockIdx.x, t = threadIdx.x;
    float v = g_f[b * 128 + t];
    s[t] = v; __syncthreads();
    for (int o = 64; o > 0; o >>= 1) { if (t < o) s[t] = fmaxf(s[t], s[t + o]); __syncthreads(); }
    float mx = s[0]; __syncthreads();
    float e = expf(v - mx);
    s[t] = e; __syncthreads();
    for (int o = 64; o > 0; o >>= 1) { if (t < o) s[t] += s[t + o]; __syncthreads(); }
    g_eout[b * 128 + t] = e / s[0];
}

// ---------------------------------------------------------------------------
// 6. Lmid[o][j] = sum_{h=1..126} manip_lin_w[o*128+h][j]
// ---------------------------------------------------------------------------
__global__ void lmid_kernel(const float* __restrict__ mlw)
{
    int idx = blockIdx.x * 256 + threadIdx.x;   // < 64*256
    int o = idx >> 8, j = idx & 255;
    float s = 0.0f;
    for (int h = 1; h <= 126; h++)
        s += mlw[(size_t)(o * 128 + h) * 256 + j];
    g_Lmid[idx] = s;
}

// ---------------------------------------------------------------------------
// 7. Manipulator + token quantization (fp32, exact as R1).
// ---------------------------------------------------------------------------
__global__ void manip_kernel(const float* __restrict__ mcw, const float* __restrict__ mcb,
                             const float* __restrict__ mlw, const float* __restrict__ mlb)
{
    __shared__ float eo[128];
    __shared__ float r[192];
    int b = blockIdx.x, t = threadIdx.x;
    if (t < 128) eo[t] = g_eout[b * 128 + t];
    __syncthreads();
    if (t < 192) {
        int g = t / 64, o = t % 64;
        float acc = mcb[o];
        for (int i = 0; i < 128; i++) {
            const float* wp = mcw + o * 1152 + i * 9;
            float w0 = wp[1], w1 = wp[4], w2 = wp[7];
            float ws = (g == 0) ? (w1 + w2) : ((g == 1) ? (w0 + w1 + w2) : (w0 + w1));
            acc += eo[i] * ws;
        }
        r[t] = fmaxf(acc, 0.0f);
    }
    __syncthreads();
    float mm = mlb[t];
    for (int o = 0; o < 64; o++) {
        mm += r[o]       * mlw[(size_t)(o * 128) * 256 + t];
        mm += r[64 + o]  * g_Lmid[o * 256 + t];
        mm += r[128 + o] * mlw[(size_t)(o * 128 + 127) * 256 + t];
    }
    g_tokens[b * 256 + t] = (int)(fmodf(floorf(fabsf(mm) * 100.0f), 14.0f));
}

// ---------------------------------------------------------------------------
// 8. Final: f @ lin2[128,14] + b2 -> softmax(14) -> out
// ---------------------------------------------------------------------------
__global__ void final_kernel(const float* __restrict__ w2, const float* __restrict__ b2,
                             float* __restrict__ out)
{
    __shared__ float fr[128];
    __shared__ float lg[14];
    int b = blockIdx.x, t = threadIdx.x;   // 32 threads
    for (int i = t; i < 128; i += 32) fr[i] = g_f[b * 128 + i];
    __syncthreads();
    if (t < 14) {
        float acc = b2[t];
        for (int j = 0; j < 128; j++) acc += fr[j] * w2[j * 14 + t];
        lg[t] = acc;
    }
    __syncthreads();
    if (t == 0) {
        float mx = lg[0];
        for (int v = 1; v < 14; v++) mx = fmaxf(mx, lg[v]);
        float s = 0.0f;
        for (int v = 0; v < 14; v++) { float e = expf(lg[v] - mx); lg[v] = e; s += e; }
        float inv = 1.0f / s;
        for (int v = 0; v < 14; v++) out[b * 14 + v] = lg[v] * inv;
    }
}

// ---------------------------------------------------------------------------
// Launch
// ---------------------------------------------------------------------------
extern "C" void kernel_launch(void* const* d_in, const int* in_sizes, int n_in,
                              void* d_out, int out_size)
{
    const int*   x       = (const int*)  d_in[0];
    const float* e_emb   = (const float*)d_in[1];
    const float* e_cw    = (const float*)d_in[2];
    const float* e_cb    = (const float*)d_in[3];
    const float* e_lw    = (const float*)d_in[4];
    const float* e_lb    = (const float*)d_in[5];
    // d_in[6] = rand_proj (dead: fog_of_war is provably identity)
    const float* m_cw    = (const float*)d_in[7];
    const float* m_cb    = (const float*)d_in[8];
    const float* m_lw    = (const float*)d_in[9];
    const float* m_lb    = (const float*)d_in[10];
    const float* f_emb   = (const float*)d_in[11];
    const float* f_cw    = (const float*)d_in[12];
    const float* f_cb    = (const float*)d_in[13];
    const float* f_lw    = (const float*)d_in[14];
    const float* f_lb    = (const float*)d_in[15];
    const float* f_l2w   = (const float*)d_in[16];
    const float* f_l2b   = (const float*)d_in[17];
    float* out = (float*)d_out;

    const int poolThreads   = BB * 130 * EMBD;   // 17,039,360
    const int repackThreads = KDIM * CO;         // 393,216

    // ---- enemy branch (3xTF32: token-exact precision) ----
    pool_kernel   <<<poolThreads / 256, 256>>>(x, e_emb);
    repack_kernel <<<repackThreads / 256, 256>>>(e_cw);
    gemm_conv_mma<true>  <<<dim3(BB, 2), 256>>>(e_cb);
    gemm_lin_mma<true>   <<<dim3(2, NSPLIT), 256>>>(e_lw);
    reduce_kernel <<<(BB * 128) / 256, 256>>>(e_lb);
    softmax128_kernel<<<BB, 128>>>();

    // ---- manipulator + tokens (fp32) ----
    lmid_kernel   <<<(64 * 256) / 256, 256>>>(m_lw);
    manip_kernel  <<<BB, 256>>>(m_cw, m_cb, m_lw, m_lb);

    // ---- friend branch (single TF32: only perturbs final logits) ----
    int* tok_dev;
    cudaGetSymbolAddress((void**)&tok_dev, g_tokens);
    pool_kernel   <<<poolThreads / 256, 256>>>(tok_dev, f_emb);
    repack_kernel <<<repackThreads / 256, 256>>>(f_cw);
    gemm_conv_mma<false> <<<dim3(BB, 2), 256>>>(f_cb);
    gemm_lin_mma<false>  <<<dim3(2, NSPLIT), 256>>>(f_lw);
    reduce_kernel <<<(BB * 128) / 256, 256>>>(f_lb);
    final_kernel  <<<BB, 32>>>(f_l2w, f_l2b, out);
}

// round 4
// speedup vs baseline: 5.1926x; 3.5462x over previous
#include <cuda_runtime.h>
#include <math.h>
#include <stdint.h>

// ---------------------------------------------------------------------------
// Constants
// ---------------------------------------------------------------------------
#define BB    256
#define LSEQ  256
#define KTOT  768        // 3 taps * 256 conv-out channels

// ---------------------------------------------------------------------------
// Static device scratch
// ---------------------------------------------------------------------------
__device__ __align__(128) float    g_VmaxT[512 * 128];      // [c][p] pairwise-max embeddings (105 pairs, padded 128)
__device__ __align__(128) uint32_t g_U2Thi[KTOT * 128];     // U[(tap,o)][p], tf32 hi
__device__ __align__(128) uint32_t g_U2Tlo[KTOT * 128];     // tf32 lo
__device__ __align__(128) uint32_t g_lwEhi[32768 * 128];    // enemy lw pre-converted tf32 hi
__device__ __align__(128) uint32_t g_lwElo[32768 * 128];    // tf32 lo
__device__ __align__(128) float    g_G[128 * 128 * 128];    // enemy table G[h][p][j]
__device__ __align__(128) float    g_Gf[128 * 128 * 16];    // friend table G[h][p][v] (lin2 folded)
__device__ __align__(128) float    g_lwF2[32768 * 16];      // friend lin1 @ lin2  [(o,h)][v]
__device__ __align__(128) float    g_tmp[256 * 128];
__device__ __align__(128) float    g_fconst[128];           // enemy bias constants
__device__ __align__(128) float    g_tmpf[256 * 16];
__device__ __align__(128) float    g_fconst2[16];           // friend logit constants
__device__ __align__(128) float    g_eout[BB * 128];
__device__ __align__(128) float    g_Lmid[64 * 256];
__device__ __align__(128) int      g_tokens[BB * LSEQ];

// ---------------------------------------------------------------------------
// MMA helpers (tf32 m16n8k8, row.col) — fragment mapping verified in R2
// ---------------------------------------------------------------------------
__device__ __forceinline__ uint32_t f2tf32(float x) {
    uint32_t r;
    asm("cvt.rna.tf32.f32 %0, %1;" : "=r"(r) : "f"(x));
    return r;
}
__device__ __forceinline__ void mma8(float* c, const uint32_t* a, const uint32_t* b) {
    asm volatile(
        "mma.sync.aligned.m16n8k8.row.col.f32.tf32.tf32.f32 "
        "{%0,%1,%2,%3}, {%4,%5,%6,%7}, {%8,%9}, {%0,%1,%2,%3};"
        : "+f"(c[0]), "+f"(c[1]), "+f"(c[2]), "+f"(c[3])
        : "r"(a[0]), "r"(a[1]), "r"(a[2]), "r"(a[3]), "r"(b[0]), "r"(b[1]));
}

// ---------------------------------------------------------------------------
// 1. VmaxT[c][p] = elementwise max of embedding pair p (dense index, a<=b)
// ---------------------------------------------------------------------------
__global__ void vmax_kernel(const float* __restrict__ emb)
{
    int idx = blockIdx.x * 256 + threadIdx.x;   // 512*128
    int c = idx >> 7, p = idx & 127;
    float v = 0.0f;
    if (p < 105) {
        int a = 0, rem = p;
        while (rem >= 14 - a) { rem -= 14 - a; a++; }
        int b = a + rem;
        v = fmaxf(emb[a * 512 + c], emb[b * 512 + c]);
    }
    g_VmaxT[idx] = v;
}

// ---------------------------------------------------------------------------
// 2. U[(tap,o)][p] = sum_c VmaxT[c][p] * cw[o][c][tap][1]  (exact fp32),
//    stored as tf32 hi/lo.
// ---------------------------------------------------------------------------
__global__ void u_kernel(const float* __restrict__ cw)
{
    __shared__ float Wcol[2][512];
    int tx = threadIdx.x, ty = threadIdx.y;
    int tid = ty * 128 + tx;
    int kbase = blockIdx.x * 2;
    for (int i = tid; i < 1024; i += 256) {
        int yy = i >> 9, c = i & 511;
        int ky = kbase + yy;                       // k = tap*256 + o
        Wcol[yy][c] = cw[(ky & 255) * 4608 + c * 9 + (ky >> 8) * 3 + 1];
    }
    __syncthreads();
    float acc = 0.0f;
#pragma unroll 8
    for (int c = 0; c < 512; c++)
        acc += g_VmaxT[c * 128 + tx] * Wcol[ty][c];
    int addr = (kbase + ty) * 128 + tx;
    uint32_t hi = f2tf32(acc);
    g_U2Thi[addr] = hi;
    g_U2Tlo[addr] = f2tf32(acc - __uint_as_float(hi));
}

// ---------------------------------------------------------------------------
// 3. Pre-convert enemy lw to tf32 hi/lo (once; reused by all 128 G blocks)
// ---------------------------------------------------------------------------
__global__ void convert_lw_kernel(const float* __restrict__ lw)
{
    int idx = blockIdx.x * 256 + threadIdx.x;   // 32768*128
    float v = lw[idx];
    uint32_t hi = f2tf32(v);
    g_lwEhi[idx] = hi;
    g_lwElo[idx] = f2tf32(v - __uint_as_float(hi));
}

// ---------------------------------------------------------------------------
// 4. Enemy G-GEMM (3xTF32). Block hh: G[hh][p][j] =
//    sum_{tap,o : 0<=hh+1-tap<128} U[(tap,o)][p] * lw[(o,hh+1-tap)][j]
//    M=128(p), N=128(j), K=768.
// ---------------------------------------------------------------------------
__global__ void __launch_bounds__(256) ggemm_e()
{
    __shared__ uint32_t As[2][16][136];
    __shared__ uint32_t Bs[2][16][136];
    float acc[2][8][4];
#pragma unroll
    for (int i = 0; i < 2; i++)
#pragma unroll
        for (int j = 0; j < 8; j++)
#pragma unroll
            for (int q = 0; q < 4; q++) acc[i][j][q] = 0.0f;

    int t    = threadIdx.x;
    int lane = t & 31;
    int wid  = t >> 5;
    int wm   = wid & 3;
    int wn   = wid >> 2;
    int gid  = lane >> 2;
    int tig  = lane & 3;
    int hh   = blockIdx.x;

    int aRow = t >> 4;            // 0..15 (k within slab)
    int aCol = (t & 15) * 8;      // p / j offset

    for (int k0 = 0; k0 < KTOT; k0 += 16) {
        {   // A slab: straight uint4 copy from U2T ([k][p] rows)
            const uint32_t* ah = g_U2Thi + (size_t)(k0 + aRow) * 128 + aCol;
            const uint32_t* al = g_U2Tlo + (size_t)(k0 + aRow) * 128 + aCol;
            *(uint4*)&As[0][aRow][aCol]     = *(const uint4*)ah;
            *(uint4*)&As[0][aRow][aCol + 4] = *(const uint4*)(ah + 4);
            *(uint4*)&As[1][aRow][aCol]     = *(const uint4*)al;
            *(uint4*)&As[1][aRow][aCol + 4] = *(const uint4*)(al + 4);
        }
        {   // B slab: gathered pre-converted lw row with tap shift + bounds
            int k   = k0 + aRow;
            int tap = k >> 8, o = k & 255;
            int h   = hh + 1 - tap;
            if (h >= 0 && h < 128) {
                size_t off = (size_t)(o * 128 + h) * 128 + aCol;
                const uint32_t* bh = g_lwEhi + off;
                const uint32_t* bl = g_lwElo + off;
                *(uint4*)&Bs[0][aRow][aCol]     = *(const uint4*)bh;
                *(uint4*)&Bs[0][aRow][aCol + 4] = *(const uint4*)(bh + 4);
                *(uint4*)&Bs[1][aRow][aCol]     = *(const uint4*)bl;
                *(uint4*)&Bs[1][aRow][aCol + 4] = *(const uint4*)(bl + 4);
            } else {
                uint4 z = make_uint4(0, 0, 0, 0);
                *(uint4*)&Bs[0][aRow][aCol]     = z;
                *(uint4*)&Bs[0][aRow][aCol + 4] = z;
                *(uint4*)&Bs[1][aRow][aCol]     = z;
                *(uint4*)&Bs[1][aRow][aCol + 4] = z;
            }
        }
        __syncthreads();

#pragma unroll
        for (int ks = 0; ks < 2; ks++) {
            int kr = ks * 8;
            uint32_t af[2][2][4];
#pragma unroll
            for (int p = 0; p < 2; p++)
#pragma unroll
                for (int mi = 0; mi < 2; mi++) {
                    int m = wm * 32 + mi * 16;
                    af[p][mi][0] = As[p][kr + tig][m + gid];
                    af[p][mi][1] = As[p][kr + tig][m + gid + 8];
                    af[p][mi][2] = As[p][kr + tig + 4][m + gid];
                    af[p][mi][3] = As[p][kr + tig + 4][m + gid + 8];
                }
#pragma unroll
            for (int nj = 0; nj < 8; nj++) {
                int n = wn * 64 + nj * 8;
                uint32_t bf[2][2];
#pragma unroll
                for (int p = 0; p < 2; p++) {
                    bf[p][0] = Bs[p][kr + tig][n + gid];
                    bf[p][1] = Bs[p][kr + tig + 4][n + gid];
                }
#pragma unroll
                for (int mi = 0; mi < 2; mi++) {
                    mma8(acc[mi][nj], af[0][mi], bf[0]);
                    mma8(acc[mi][nj], af[0][mi], bf[1]);
                    mma8(acc[mi][nj], af[1][mi], bf[0]);
                }
            }
        }
        __syncthreads();
    }

    float* gbase = g_G + (size_t)hh * (128 * 128);
#pragma unroll
    for (int mi = 0; mi < 2; mi++) {
        int m = wm * 32 + mi * 16 + gid;
#pragma unroll
        for (int nj = 0; nj < 8; nj++) {
            int n = wn * 64 + nj * 8 + 2 * tig;
            gbase[(size_t)m * 128 + n]           = acc[mi][nj][0];
            gbase[(size_t)m * 128 + n + 1]       = acc[mi][nj][1];
            gbase[(size_t)(m + 8) * 128 + n]     = acc[mi][nj][2];
            gbase[(size_t)(m + 8) * 128 + n + 1] = acc[mi][nj][3];
        }
    }
}

// ---------------------------------------------------------------------------
// 5. Friend: fold lin2 into lin1: lwF2[(o,h)][v] = sum_j lw1[(o,h)][j]*l2w[j][v]
// ---------------------------------------------------------------------------
__global__ void lwf2_kernel(const float* __restrict__ lw1, const float* __restrict__ l2w)
{
    __shared__ float lr[16][128];
    __shared__ float l2[128][16];
    int t = threadIdx.x, bx = blockIdx.x;   // 2048 blocks, 16 rows each
    for (int i = t; i < 2048; i += 256)
        lr[i >> 7][i & 127] = lw1[(size_t)bx * 2048 + i];
    for (int i = t; i < 2048; i += 256) {
        int j = i >> 4, v = i & 15;
        l2[j][v] = (v < 14) ? l2w[j * 14 + v] : 0.0f;
    }
    __syncthreads();
    int r = t >> 4, v = t & 15;
    float acc = 0.0f;
#pragma unroll 8
    for (int j = 0; j < 128; j++)
        acc += lr[r][j] * l2[j][v];
    g_lwF2[(size_t)(bx * 16 + r) * 16 + v] = acc;
}

// ---------------------------------------------------------------------------
// 6. Friend G-GEMM (single TF32): M=128(p), N=16(v), K=768, per block hh.
// ---------------------------------------------------------------------------
__global__ void __launch_bounds__(128) ggemm_f()
{
    __shared__ uint32_t As[16][136];
    __shared__ uint32_t Bs[16][24];
    float acc[2][2][4];
#pragma unroll
    for (int i = 0; i < 2; i++)
#pragma unroll
        for (int j = 0; j < 2; j++)
#pragma unroll
            for (int q = 0; q < 4; q++) acc[i][j][q] = 0.0f;

    int t    = threadIdx.x;
    int lane = t & 31;
    int wm   = t >> 5;            // 4 warps: M rows wm*32
    int gid  = lane >> 2;
    int tig  = lane & 3;
    int hh   = blockIdx.x;

    int aRow = t >> 3;            // 0..15
    int aCol = (t & 7) * 16;      // 16 p's per thread
    int bCol = (t & 7) * 2;       // 2 v's per thread

    for (int k0 = 0; k0 < KTOT; k0 += 16) {
        {
            const uint32_t* ah = g_U2Thi + (size_t)(k0 + aRow) * 128 + aCol;
#pragma unroll
            for (int q = 0; q < 4; q++)
                *(uint4*)&As[aRow][aCol + q * 4] = *(const uint4*)(ah + q * 4);
        }
        {
            int k   = k0 + aRow;
            int tap = k >> 8, o = k & 255;
            int h   = hh + 1 - tap;
            float v0 = 0.0f, v1 = 0.0f;
            if (h >= 0 && h < 128) {
                const float* bp = g_lwF2 + (size_t)(o * 128 + h) * 16 + bCol;
                v0 = bp[0]; v1 = bp[1];
            }
            Bs[aRow][bCol]     = f2tf32(v0);
            Bs[aRow][bCol + 1] = f2tf32(v1);
        }
        __syncthreads();

#pragma unroll
        for (int ks = 0; ks < 2; ks++) {
            int kr = ks * 8;
            uint32_t af[2][4];
#pragma unroll
            for (int mi = 0; mi < 2; mi++) {
                int m = wm * 32 + mi * 16;
                af[mi][0] = As[kr + tig][m + gid];
                af[mi][1] = As[kr + tig][m + gid + 8];
                af[mi][2] = As[kr + tig + 4][m + gid];
                af[mi][3] = As[kr + tig + 4][m + gid + 8];
            }
#pragma unroll
            for (int nj = 0; nj < 2; nj++) {
                int n = nj * 8;
                uint32_t bf[2];
                bf[0] = Bs[kr + tig][n + gid];
                bf[1] = Bs[kr + tig + 4][n + gid];
#pragma unroll
                for (int mi = 0; mi < 2; mi++)
                    mma8(acc[mi][nj], af[mi], bf);
            }
        }
        __syncthreads();
    }

    float* gbase = g_Gf + (size_t)hh * (128 * 16);
#pragma unroll
    for (int mi = 0; mi < 2; mi++) {
        int m = wm * 32 + mi * 16 + gid;
#pragma unroll
        for (int nj = 0; nj < 2; nj++) {
            int n = nj * 8 + 2 * tig;
            gbase[m * 16 + n]           = acc[mi][nj][0];
            gbase[m * 16 + n + 1]       = acc[mi][nj][1];
            gbase[(m + 8) * 16 + n]     = acc[mi][nj][2];
            gbase[(m + 8) * 16 + n + 1] = acc[mi][nj][3];
        }
    }
}

// ---------------------------------------------------------------------------
// 7. Bias constants
// ---------------------------------------------------------------------------
__global__ void lsum1_kernel(const float* __restrict__ lw, const float* __restrict__ cb)
{
    int o = blockIdx.x, j = threadIdx.x;
    float acc = 0.0f;
    for (int h = 0; h < 128; h++)
        acc += lw[(size_t)(o * 128 + h) * 128 + j];
    g_tmp[o * 128 + j] = cb[o] * acc;
}
__global__ void lsum2_kernel(const float* __restrict__ lb)
{
    int j = threadIdx.x;
    float s = lb[j];
    for (int o = 0; o < 256; o++) s += g_tmp[o * 128 + j];
    g_fconst[j] = s;
}
__global__ void fc2a_kernel(const float* __restrict__ cbf)
{
    int o = blockIdx.x * 8 + (threadIdx.x >> 4), v = threadIdx.x & 15;
    float acc = 0.0f;
    for (int h = 0; h < 128; h++)
        acc += g_lwF2[(size_t)(o * 128 + h) * 16 + v];
    g_tmpf[o * 16 + v] = cbf[o] * acc;
}
__global__ void fc2b_kernel(const float* __restrict__ lb1, const float* __restrict__ l2w,
                            const float* __restrict__ l2b)
{
    int v = threadIdx.x;   // 16
    float s = 0.0f;
    if (v < 14) {
        s = l2b[v];
        for (int j = 0; j < 128; j++) s += lb1[j] * l2w[j * 14 + v];
    }
    for (int o = 0; o < 256; o++) s += g_tmpf[o * 16 + v];
    g_fconst2[v] = (v < 14) ? s : 0.0f;
}

// ---------------------------------------------------------------------------
// 8. Enemy gather-sum + softmax -> g_eout
// ---------------------------------------------------------------------------
__global__ void gather_e_kernel(const int* __restrict__ x)
{
    __shared__ int   sp[128];
    __shared__ float red[128];
    int b = blockIdx.x, t = threadIdx.x;
    {
        int t0 = x[b * 256 + 2 * t], t1 = x[b * 256 + 2 * t + 1];
        int a = min(t0, t1), bb = max(t0, t1);
        sp[t] = a * 14 + bb - ((a * (a + 1)) >> 1);   // dense pair index
    }
    __syncthreads();
    float acc = g_fconst[t];
#pragma unroll 4
    for (int h = 0; h < 128; h++)
        acc += g_G[(size_t)((h << 7) + sp[h]) * 128 + t];
    red[t] = acc; __syncthreads();
    for (int o = 64; o > 0; o >>= 1) { if (t < o) red[t] = fmaxf(red[t], red[t + o]); __syncthreads(); }
    float mx = red[0]; __syncthreads();
    float e = expf(acc - mx);
    red[t] = e; __syncthreads();
    for (int o = 64; o > 0; o >>= 1) { if (t < o) red[t] += red[t + o]; __syncthreads(); }
    g_eout[b * 128 + t] = e / red[0];
}

// ---------------------------------------------------------------------------
// 9. Lmid + manipulator (fp32 exact; unchanged, proven in R1/R2)
// ---------------------------------------------------------------------------
__global__ void lmid_kernel(const float* __restrict__ mlw)
{
    int idx = blockIdx.x * 256 + threadIdx.x;   // 64*256
    int o = idx >> 8, j = idx & 255;
    float s = 0.0f;
    for (int h = 1; h <= 126; h++)
        s += mlw[(size_t)(o * 128 + h) * 256 + j];
    g_Lmid[idx] = s;
}
__global__ void manip_kernel(const float* __restrict__ mcw, const float* __restrict__ mcb,
                             const float* __restrict__ mlw, const float* __restrict__ mlb)
{
    __shared__ float eo[128];
    __shared__ float r[192];
    int b = blockIdx.x, t = threadIdx.x;
    if (t < 128) eo[t] = g_eout[b * 128 + t];
    __syncthreads();
    if (t < 192) {
        int g = t / 64, o = t % 64;
        float acc = mcb[o];
        for (int i = 0; i < 128; i++) {
            const float* wp = mcw + o * 1152 + i * 9;
            float w0 = wp[1], w1 = wp[4], w2 = wp[7];
            float ws = (g == 0) ? (w1 + w2) : ((g == 1) ? (w0 + w1 + w2) : (w0 + w1));
            acc += eo[i] * ws;
        }
        r[t] = fmaxf(acc, 0.0f);
    }
    __syncthreads();
    float mm = mlb[t];
    for (int o = 0; o < 64; o++) {
        mm += r[o]       * mlw[(size_t)(o * 128) * 256 + t];
        mm += r[64 + o]  * g_Lmid[o * 256 + t];
        mm += r[128 + o] * mlw[(size_t)(o * 128 + 127) * 256 + t];
    }
    g_tokens[b * 256 + t] = (int)(fmodf(floorf(fabsf(mm) * 100.0f), 14.0f));
}

// ---------------------------------------------------------------------------
// 10. Friend gather-sum + final softmax -> out
// ---------------------------------------------------------------------------
__global__ void gather_f_kernel(float* __restrict__ out)
{
    __shared__ int   sp[128];
    __shared__ float part[128];
    __shared__ float lg[16];
    int b = blockIdx.x, t = threadIdx.x;
    {
        int t0 = g_tokens[b * 256 + 2 * t], t1 = g_tokens[b * 256 + 2 * t + 1];
        int a = min(t0, t1), bb = max(t0, t1);
        sp[t] = a * 14 + bb - ((a * (a + 1)) >> 1);
    }
    __syncthreads();
    int v = t & 15, hg = t >> 4;
    float ps = 0.0f;
#pragma unroll 4
    for (int i = 0; i < 16; i++) {
        int h = hg * 16 + i;
        ps += g_Gf[(size_t)((h << 7) + sp[h]) * 16 + v];
    }
    part[t] = ps; __syncthreads();
    if (t < 16) {
        float s = g_fconst2[t];
        for (int g = 0; g < 8; g++) s += part[g * 16 + t];
        lg[t] = s;
    }
    __syncthreads();
    if (t == 0) {
        float mx = lg[0];
        for (int q = 1; q < 14; q++) mx = fmaxf(mx, lg[q]);
        float sum = 0.0f;
        for (int q = 0; q < 14; q++) { float e = expf(lg[q] - mx); lg[q] = e; sum += e; }
        float inv = 1.0f / sum;
        for (int q = 0; q < 14; q++) out[b * 14 + q] = lg[q] * inv;
    }
}

// ---------------------------------------------------------------------------
// Launch (single stream; ordering carries all dependencies)
// ---------------------------------------------------------------------------
extern "C" void kernel_launch(void* const* d_in, const int* in_sizes, int n_in,
                              void* d_out, int out_size)
{
    const int*   x     = (const int*)  d_in[0];
    const float* e_emb = (const float*)d_in[1];
    const float* e_cw  = (const float*)d_in[2];
    const float* e_cb  = (const float*)d_in[3];
    const float* e_lw  = (const float*)d_in[4];
    const float* e_lb  = (const float*)d_in[5];
    // d_in[6] = rand_proj (dead: fog_of_war is provably identity)
    const float* m_cw  = (const float*)d_in[7];
    const float* m_cb  = (const float*)d_in[8];
    const float* m_lw  = (const float*)d_in[9];
    const float* m_lb  = (const float*)d_in[10];
    const float* f_emb = (const float*)d_in[11];
    const float* f_cw  = (const float*)d_in[12];
    const float* f_cb  = (const float*)d_in[13];
    const float* f_lw  = (const float*)d_in[14];
    const float* f_lb  = (const float*)d_in[15];
    const float* f_l2w = (const float*)d_in[16];
    const float* f_l2b = (const float*)d_in[17];
    float* out = (float*)d_out;

    // ---- enemy branch: build table, gather, softmax ----
    vmax_kernel      <<<256, 256>>>(e_emb);
    u_kernel         <<<384, dim3(128, 2)>>>(e_cw);
    convert_lw_kernel<<<16384, 256>>>(e_lw);
    ggemm_e          <<<128, 256>>>();
    lsum1_kernel     <<<256, 128>>>(e_lw, e_cb);
    lsum2_kernel     <<<1, 128>>>(e_lb);
    gather_e_kernel  <<<BB, 128>>>(x);

    // ---- manipulator -> tokens (fp32 exact) ----
    lmid_kernel      <<<64, 256>>>(m_lw);
    manip_kernel     <<<BB, 256>>>(m_cw, m_cb, m_lw, m_lb);

    // ---- friend branch: rebuild table for friend weights, gather, out ----
    vmax_kernel      <<<256, 256>>>(f_emb);
    u_kernel         <<<384, dim3(128, 2)>>>(f_cw);
    lwf2_kernel      <<<2048, 256>>>(f_lw, f_l2w);
    ggemm_f          <<<128, 128>>>();
    fc2a_kernel      <<<32, 128>>>(f_cb);
    fc2b_kernel      <<<1, 16>>>(f_lb, f_l2w, f_l2b);
    gather_f_kernel  <<<BB, 128>>>(out);
}

// round 6
// speedup vs baseline: 5.6359x; 1.0854x over previous
#include <cuda_runtime.h>
#include <math.h>
#include <stdint.h>

// ---------------------------------------------------------------------------
// Constants
// ---------------------------------------------------------------------------
#define BB    256
#define LSEQ  256
#define KTOT  768        // 3 taps * 256 conv-out channels

// ---------------------------------------------------------------------------
// Static device scratch
// ---------------------------------------------------------------------------
__device__ __align__(128) float    g_VmaxT[512 * 128];      // [c][p] pairwise-max embeddings
__device__ __align__(128) uint32_t g_U2Thi[KTOT * 128];     // U[(tap,o)][p], tf32 hi
__device__ __align__(128) uint32_t g_U2Tlo[KTOT * 128];     // tf32 lo
__device__ __align__(128) uint32_t g_lwEhi[32768 * 128];    // enemy lw tf32 hi
__device__ __align__(128) uint32_t g_lwElo[32768 * 128];    // tf32 lo
__device__ __align__(128) float    g_G[128 * 128 * 128];    // enemy table G[h][p][j]
__device__ __align__(128) float    g_Gf[128 * 128 * 16];    // friend table G[h][p][v]
__device__ __align__(128) float    g_lwF2[32768 * 16];      // friend lin1 @ lin2
__device__ __align__(128) float    g_tmp[256 * 128];
__device__ __align__(128) float    g_fconst[128];
__device__ __align__(128) float    g_tmpf[256 * 16];
__device__ __align__(128) float    g_fconst2[16];
__device__ __align__(128) float    g_eout[BB * 128];
__device__ __align__(128) float    g_Lmid[64 * 256];
__device__ __align__(128) int      g_tokens[BB * LSEQ];

// ---------------------------------------------------------------------------
// Helpers
// ---------------------------------------------------------------------------
__device__ __forceinline__ uint32_t f2tf32(float x) {
    uint32_t r;
    asm("cvt.rna.tf32.f32 %0, %1;" : "=r"(r) : "f"(x));
    return r;
}
__device__ __forceinline__ void mma8(float* c, const uint32_t* a, const uint32_t* b) {
    asm volatile(
        "mma.sync.aligned.m16n8k8.row.col.f32.tf32.tf32.f32 "
        "{%0,%1,%2,%3}, {%4,%5,%6,%7}, {%8,%9}, {%0,%1,%2,%3};"
        : "+f"(c[0]), "+f"(c[1]), "+f"(c[2]), "+f"(c[3])
        : "r"(a[0]), "r"(a[1]), "r"(a[2]), "r"(a[3]), "r"(b[0]), "r"(b[1]));
}
__device__ __forceinline__ void cp16(uint32_t saddr, const void* g) {
    asm volatile("cp.async.cg.shared.global [%0], [%1], 16;" :: "r"(saddr), "l"(g));
}
__device__ __forceinline__ void cp16z(uint32_t saddr, const void* g, int srcsz) {
    asm volatile("cp.async.cg.shared.global [%0], [%1], 16, %2;"
                 :: "r"(saddr), "l"(g), "r"(srcsz));
}
__device__ __forceinline__ void cp_commit() {
    asm volatile("cp.async.commit_group;");
}

// ---------------------------------------------------------------------------
// 1. VmaxT[c][p] = elementwise max of embedding pair p (dense, a<=b)
// ---------------------------------------------------------------------------
__global__ void vmax_kernel(const float* __restrict__ emb)
{
    int idx = blockIdx.x * 256 + threadIdx.x;   // 512*128
    int c = idx >> 7, p = idx & 127;
    float v = 0.0f;
    if (p < 105) {
        int a = 0, rem = p;
        while (rem >= 14 - a) { rem -= 14 - a; a++; }
        int b = a + rem;
        v = fmaxf(emb[a * 512 + c], emb[b * 512 + c]);
    }
    g_VmaxT[idx] = v;
}

// ---------------------------------------------------------------------------
// 2. U[(tap,o)][p] = sum_c VmaxT[c][p] * cw[o][c][tap][1]  (exact fp32)
// ---------------------------------------------------------------------------
__global__ void u_kernel(const float* __restrict__ cw)
{
    __shared__ float Wcol[2][512];
    int tx = threadIdx.x, ty = threadIdx.y;
    int tid = ty * 128 + tx;
    int kbase = blockIdx.x * 2;
    for (int i = tid; i < 1024; i += 256) {
        int yy = i >> 9, c = i & 511;
        int ky = kbase + yy;
        Wcol[yy][c] = cw[(ky & 255) * 4608 + c * 9 + (ky >> 8) * 3 + 1];
    }
    __syncthreads();
    float acc = 0.0f;
#pragma unroll 8
    for (int c = 0; c < 512; c++)
        acc += g_VmaxT[c * 128 + tx] * Wcol[ty][c];
    int addr = (kbase + ty) * 128 + tx;
    uint32_t hi = f2tf32(acc);
    g_U2Thi[addr] = hi;
    g_U2Tlo[addr] = f2tf32(acc - __uint_as_float(hi));
}

// ---------------------------------------------------------------------------
// 3. Pre-convert enemy lw to tf32 hi/lo
// ---------------------------------------------------------------------------
__global__ void convert_lw_kernel(const float* __restrict__ lw)
{
    int idx = blockIdx.x * 256 + threadIdx.x;   // 32768*128
    float v = lw[idx];
    uint32_t hi = f2tf32(v);
    g_lwEhi[idx] = hi;
    g_lwElo[idx] = f2tf32(v - __uint_as_float(hi));
}

// ---------------------------------------------------------------------------
// 4. Enemy G-GEMM (3xTF32), 2-stage cp.async double buffer.
//    Block hh: G[hh][p][j] = sum_{tap,o} U[(tap,o)][p] * lw[(o,hh+1-tap)][j]
//    Dyn smem (uint32 words): A[2 stage][2 plane][16][136], B likewise.
// ---------------------------------------------------------------------------
#define PLW 2176                 // 16*136 words per plane
#define SME_BYTES (8 * PLW * 4)  // 69632

__global__ void __launch_bounds__(256) ggemm_e()
{
    extern __shared__ uint32_t sm[];
    const int BOFF = 4 * PLW;

    float acc[2][8][4];
#pragma unroll
    for (int i = 0; i < 2; i++)
#pragma unroll
        for (int j = 0; j < 8; j++)
#pragma unroll
            for (int q = 0; q < 4; q++) acc[i][j][q] = 0.0f;

    int t    = threadIdx.x;
    int lane = t & 31;
    int wid  = t >> 5;
    int wm   = wid & 3;
    int wn   = wid >> 2;
    int gid  = lane >> 2;
    int tig  = lane & 3;
    int hh   = blockIdx.x;

    uint32_t sbase = (uint32_t)__cvta_generic_to_shared(sm);

    auto load_stage = [&](int s, int k0) {
#pragma unroll
        for (int pl = 0; pl < 2; pl++) {
#pragma unroll
            for (int q = 0; q < 2; q++) {
                int c   = t * 2 + q;           // 0..511
                int row = c >> 5;
                int c4  = (c & 31) * 4;
                uint32_t sa = sbase + (uint32_t)(((s * 2 + pl) * PLW + row * 136 + c4) * 4);
                const uint32_t* g = (pl ? g_U2Tlo : g_U2Thi) + (size_t)(k0 + row) * 128 + c4;
                cp16(sa, g);
            }
        }
#pragma unroll
        for (int q = 0; q < 2; q++) {
            int c   = t * 2 + q;
            int row = c >> 5;
            int c4  = (c & 31) * 4;
            int k   = k0 + row;
            int tap = k >> 8, o = k & 255;
            int h   = hh + 1 - tap;
            int ok  = (h >= 0 && h < 128) ? 16 : 0;
            size_t off = ok ? ((size_t)(o * 128 + h) * 128 + c4) : 0;
#pragma unroll
            for (int pl = 0; pl < 2; pl++) {
                uint32_t sa = sbase + (uint32_t)((BOFF + (s * 2 + pl) * PLW + row * 136 + c4) * 4);
                const uint32_t* g = (pl ? g_lwElo : g_lwEhi) + off;
                cp16z(sa, g, ok);
            }
        }
        cp_commit();
    };

    const int NIT = KTOT / 16;   // 48
    load_stage(0, 0);

    for (int it = 0; it < NIT; it++) {
        if (it + 1 < NIT) {
            load_stage((it + 1) & 1, (it + 1) * 16);
            asm volatile("cp.async.wait_group 1;");
        } else {
            asm volatile("cp.async.wait_group 0;");
        }
        __syncthreads();

        int s = it & 1;
        const uint32_t* A0 = sm + (s * 2 + 0) * PLW;
        const uint32_t* A1 = sm + (s * 2 + 1) * PLW;
        const uint32_t* B0 = sm + BOFF + (s * 2 + 0) * PLW;
        const uint32_t* B1 = sm + BOFF + (s * 2 + 1) * PLW;

#pragma unroll
        for (int ks = 0; ks < 2; ks++) {
            int kr = ks * 8;
            uint32_t af[2][2][4];
#pragma unroll
            for (int mi = 0; mi < 2; mi++) {
                int m = wm * 32 + mi * 16;
                af[0][mi][0] = A0[(kr + tig) * 136 + m + gid];
                af[0][mi][1] = A0[(kr + tig) * 136 + m + gid + 8];
                af[0][mi][2] = A0[(kr + tig + 4) * 136 + m + gid];
                af[0][mi][3] = A0[(kr + tig + 4) * 136 + m + gid + 8];
                af[1][mi][0] = A1[(kr + tig) * 136 + m + gid];
                af[1][mi][1] = A1[(kr + tig) * 136 + m + gid + 8];
                af[1][mi][2] = A1[(kr + tig + 4) * 136 + m + gid];
                af[1][mi][3] = A1[(kr + tig + 4) * 136 + m + gid + 8];
            }
#pragma unroll
            for (int nj = 0; nj < 8; nj++) {
                int n = wn * 64 + nj * 8;
                uint32_t bf[2][2];
                bf[0][0] = B0[(kr + tig) * 136 + n + gid];
                bf[0][1] = B0[(kr + tig + 4) * 136 + n + gid];
                bf[1][0] = B1[(kr + tig) * 136 + n + gid];
                bf[1][1] = B1[(kr + tig + 4) * 136 + n + gid];
#pragma unroll
                for (int mi = 0; mi < 2; mi++) {
                    mma8(acc[mi][nj], af[0][mi], bf[0]);
                    mma8(acc[mi][nj], af[0][mi], bf[1]);
                    mma8(acc[mi][nj], af[1][mi], bf[0]);
                }
            }
        }
        __syncthreads();
    }

    float* gbase = g_G + (size_t)hh * (128 * 128);
#pragma unroll
    for (int mi = 0; mi < 2; mi++) {
        int m = wm * 32 + mi * 16 + gid;
#pragma unroll
        for (int nj = 0; nj < 8; nj++) {
            int n = wn * 64 + nj * 8 + 2 * tig;
            gbase[(size_t)m * 128 + n]           = acc[mi][nj][0];
            gbase[(size_t)m * 128 + n + 1]       = acc[mi][nj][1];
            gbase[(size_t)(m + 8) * 128 + n]     = acc[mi][nj][2];
            gbase[(size_t)(m + 8) * 128 + n + 1] = acc[mi][nj][3];
        }
    }
}

// ---------------------------------------------------------------------------
// 5. Friend: lwF2[(o,h)][v] = sum_j lw1[(o,h)][j]*l2w[j][v]
// ---------------------------------------------------------------------------
__global__ void lwf2_kernel(const float* __restrict__ lw1, const float* __restrict__ l2w)
{
    __shared__ float lr[16][128];
    __shared__ float l2[128][16];
    int t = threadIdx.x, bx = blockIdx.x;
    for (int i = t; i < 2048; i += 256)
        lr[i >> 7][i & 127] = lw1[(size_t)bx * 2048 + i];
    for (int i = t; i < 2048; i += 256) {
        int j = i >> 4, v = i & 15;
        l2[j][v] = (v < 14) ? l2w[j * 14 + v] : 0.0f;
    }
    __syncthreads();
    int r = t >> 4, v = t & 15;
    float acc = 0.0f;
#pragma unroll 8
    for (int j = 0; j < 128; j++)
        acc += lr[r][j] * l2[j][v];
    g_lwF2[(size_t)(bx * 16 + r) * 16 + v] = acc;
}

// ---------------------------------------------------------------------------
// 6. Friend G-GEMM (single TF32), 2-stage cp.async double buffer.
// ---------------------------------------------------------------------------
__global__ void __launch_bounds__(128) ggemm_f()
{
    __shared__ uint32_t Asm[2][16][136];
    __shared__ uint32_t Bsm[2][16][24];

    float acc[2][2][4];
#pragma unroll
    for (int i = 0; i < 2; i++)
#pragma unroll
        for (int j = 0; j < 2; j++)
#pragma unroll
            for (int q = 0; q < 4; q++) acc[i][j][q] = 0.0f;

    int t    = threadIdx.x;
    int lane = t & 31;
    int wm   = t >> 5;
    int gid  = lane >> 2;
    int tig  = lane & 3;
    int hh   = blockIdx.x;

    uint32_t saA = (uint32_t)__cvta_generic_to_shared(&Asm[0][0][0]);
    uint32_t saB = (uint32_t)__cvta_generic_to_shared(&Bsm[0][0][0]);

    auto load_stage = [&](int s, int k0) {
#pragma unroll
        for (int q = 0; q < 4; q++) {
            int c   = t * 4 + q;
            int row = c >> 5;
            int c4  = (c & 31) * 4;
            uint32_t sa = saA + (uint32_t)((s * 16 * 136 + row * 136 + c4) * 4);
            const uint32_t* g = g_U2Thi + (size_t)(k0 + row) * 128 + c4;
            cp16(sa, g);
        }
        if (t < 64) {
            int row = t >> 2;
            int c4  = (t & 3) * 4;
            int k   = k0 + row;
            int tap = k >> 8, o = k & 255;
            int h   = hh + 1 - tap;
            int ok  = (h >= 0 && h < 128) ? 16 : 0;
            size_t off = ok ? ((size_t)(o * 128 + h) * 16 + c4) : 0;
            uint32_t sa = saB + (uint32_t)((s * 16 * 24 + row * 24 + c4) * 4);
            cp16z(sa, (const uint32_t*)g_lwF2 + off, ok);
        }
        cp_commit();
    };

    const int NIT = KTOT / 16;
    load_stage(0, 0);

    for (int it = 0; it < NIT; it++) {
        if (it + 1 < NIT) {
            load_stage((it + 1) & 1, (it + 1) * 16);
            asm volatile("cp.async.wait_group 1;");
        } else {
            asm volatile("cp.async.wait_group 0;");
        }
        __syncthreads();
        int s = it & 1;

#pragma unroll
        for (int ks = 0; ks < 2; ks++) {
            int kr = ks * 8;
            uint32_t af[2][4];
#pragma unroll
            for (int mi = 0; mi < 2; mi++) {
                int m = wm * 32 + mi * 16;
                af[mi][0] = Asm[s][kr + tig][m + gid];
                af[mi][1] = Asm[s][kr + tig][m + gid + 8];
                af[mi][2] = Asm[s][kr + tig + 4][m + gid];
                af[mi][3] = Asm[s][kr + tig + 4][m + gid + 8];
            }
#pragma unroll
            for (int nj = 0; nj < 2; nj++) {
                int n = nj * 8;
                uint32_t bf[2];
                bf[0] = f2tf32(__uint_as_float(Bsm[s][kr + tig][n + gid]));
                bf[1] = f2tf32(__uint_as_float(Bsm[s][kr + tig + 4][n + gid]));
#pragma unroll
                for (int mi = 0; mi < 2; mi++)
                    mma8(acc[mi][nj], af[mi], bf);
            }
        }
        __syncthreads();
    }

    float* gbase = g_Gf + (size_t)hh * (128 * 16);
#pragma unroll
    for (int mi = 0; mi < 2; mi++) {
        int m = wm * 32 + mi * 16 + gid;
#pragma unroll
        for (int nj = 0; nj < 2; nj++) {
            int n = nj * 8 + 2 * tig;
            gbase[m * 16 + n]           = acc[mi][nj][0];
            gbase[m * 16 + n + 1]       = acc[mi][nj][1];
            gbase[(m + 8) * 16 + n]     = acc[mi][nj][2];
            gbase[(m + 8) * 16 + n + 1] = acc[mi][nj][3];
        }
    }
}

// ---------------------------------------------------------------------------
// 7. Bias constants
// ---------------------------------------------------------------------------
__global__ void lsum1_kernel(const float* __restrict__ lw, const float* __restrict__ cb)
{
    int o = blockIdx.x, j = threadIdx.x;
    float acc = 0.0f;
    for (int h = 0; h < 128; h++)
        acc += lw[(size_t)(o * 128 + h) * 128 + j];
    g_tmp[o * 128 + j] = cb[o] * acc;
}
__global__ void lsum2_kernel(const float* __restrict__ lb)
{
    int j = threadIdx.x;
    float s = lb[j];
    for (int o = 0; o < 256; o++) s += g_tmp[o * 128 + j];
    g_fconst[j] = s;
}
__global__ void fc2a_kernel(const float* __restrict__ cbf)
{
    int o = blockIdx.x * 8 + (threadIdx.x >> 4), v = threadIdx.x & 15;
    float acc = 0.0f;
    for (int h = 0; h < 128; h++)
        acc += g_lwF2[(size_t)(o * 128 + h) * 16 + v];
    g_tmpf[o * 16 + v] = cbf[o] * acc;
}
__global__ void fc2b_kernel(const float* __restrict__ lb1, const float* __restrict__ l2w,
                            const float* __restrict__ l2b)
{
    int v = threadIdx.x;   // 16
    float s = 0.0f;
    if (v < 14) {
        s = l2b[v];
        for (int j = 0; j < 128; j++) s += lb1[j] * l2w[j * 14 + v];
    }
    for (int o = 0; o < 256; o++) s += g_tmpf[o * 16 + v];
    g_fconst2[v] = (v < 14) ? s : 0.0f;
}

// ---------------------------------------------------------------------------
// 8. Enemy gather-sum + softmax -> g_eout
// ---------------------------------------------------------------------------
__global__ void gather_e_kernel(const int* __restrict__ x)
{
    __shared__ int   sp[128];
    __shared__ float red[128];
    int b = blockIdx.x, t = threadIdx.x;
    {
        int t0 = x[b * 256 + 2 * t], t1 = x[b * 256 + 2 * t + 1];
        int a = min(t0, t1), bb = max(t0, t1);
        sp[t] = a * 14 + bb - ((a * (a + 1)) >> 1);
    }
    __syncthreads();
    float acc = g_fconst[t];
#pragma unroll 4
    for (int h = 0; h < 128; h++)
        acc += g_G[(size_t)((h << 7) + sp[h]) * 128 + t];
    red[t] = acc; __syncthreads();
    for (int o = 64; o > 0; o >>= 1) { if (t < o) red[t] = fmaxf(red[t], red[t + o]); __syncthreads(); }
    float mx = red[0]; __syncthreads();
    float e = expf(acc - mx);
    red[t] = e; __syncthreads();
    for (int o = 64; o > 0; o >>= 1) { if (t < o) red[t] += red[t + o]; __syncthreads(); }
    g_eout[b * 128 + t] = e / red[0];
}

// ---------------------------------------------------------------------------
// 9. Lmid + manipulator (fp32 exact)
// ---------------------------------------------------------------------------
__global__ void lmid_kernel(const float* __restrict__ mlw)
{
    int idx = blockIdx.x * 256 + threadIdx.x;
    int o = idx >> 8, j = idx & 255;
    float s = 0.0f;
    for (int h = 1; h <= 126; h++)
        s += mlw[(size_t)(o * 128 + h) * 256 + j];
    g_Lmid[idx] = s;
}
__global__ void manip_kernel(const float* __restrict__ mcw, const float* __restrict__ mcb,
                             const float* __restrict__ mlw, const float* __restrict__ mlb)
{
    __shared__ float eo[128];
    __shared__ float r[192];
    int b = blockIdx.x, t = threadIdx.x;
    if (t < 128) eo[t] = g_eout[b * 128 + t];
    __syncthreads();
    if (t < 192) {
        int g = t / 64, o = t % 64;
        float acc = mcb[o];
        for (int i = 0; i < 128; i++) {
            const float* wp = mcw + o * 1152 + i * 9;
            float w0 = wp[1], w1 = wp[4], w2 = wp[7];
            float ws = (g == 0) ? (w1 + w2) : ((g == 1) ? (w0 + w1 + w2) : (w0 + w1));
            acc += eo[i] * ws;
        }
        r[t] = fmaxf(acc, 0.0f);
    }
    __syncthreads();
    float mm = mlb[t];
    for (int o = 0; o < 64; o++) {
        mm += r[o]       * mlw[(size_t)(o * 128) * 256 + t];
        mm += r[64 + o]  * g_Lmid[o * 256 + t];
        mm += r[128 + o] * mlw[(size_t)(o * 128 + 127) * 256 + t];
    }
    g_tokens[b * 256 + t] = (int)(fmodf(floorf(fabsf(mm) * 100.0f), 14.0f));
}

// ---------------------------------------------------------------------------
// 10. Friend gather-sum + final softmax -> out
// ---------------------------------------------------------------------------
__global__ void gather_f_kernel(float* __restrict__ out)
{
    __shared__ int   sp[128];
    __shared__ float part[128];
    __shared__ float lg[16];
    int b = blockIdx.x, t = threadIdx.x;
    {
        int t0 = g_tokens[b * 256 + 2 * t], t1 = g_tokens[b * 256 + 2 * t + 1];
        int a = min(t0, t1), bb = max(t0, t1);
        sp[t] = a * 14 + bb - ((a * (a + 1)) >> 1);
    }
    __syncthreads();
    int v = t & 15, hg = t >> 4;
    float ps = 0.0f;
#pragma unroll 4
    for (int i = 0; i < 16; i++) {
        int h = hg * 16 + i;
        ps += g_Gf[(size_t)((h << 7) + sp[h]) * 16 + v];
    }
    part[t] = ps; __syncthreads();
    if (t < 16) {
        float s = g_fconst2[t];
        for (int g = 0; g < 8; g++) s += part[g * 16 + t];
        lg[t] = s;
    }
    __syncthreads();
    if (t == 0) {
        float mx = lg[0];
        for (int q = 1; q < 14; q++) mx = fmaxf(mx, lg[q]);
        float sum = 0.0f;
        for (int q = 0; q < 14; q++) { float e = expf(lg[q] - mx); lg[q] = e; sum += e; }
        float inv = 1.0f / sum;
        for (int q = 0; q < 14; q++) out[b * 14 + q] = lg[q] * inv;
    }
}

// ---------------------------------------------------------------------------
// Launch
// ---------------------------------------------------------------------------
extern "C" void kernel_launch(void* const* d_in, const int* in_sizes, int n_in,
                              void* d_out, int out_size)
{
    const int*   x     = (const int*)  d_in[0];
    const float* e_emb = (const float*)d_in[1];
    const float* e_cw  = (const float*)d_in[2];
    const float* e_cb  = (const float*)d_in[3];
    const float* e_lw  = (const float*)d_in[4];
    const float* e_lb  = (const float*)d_in[5];
    // d_in[6] = rand_proj (dead: fog_of_war is provably identity)
    const float* m_cw  = (const float*)d_in[7];
    const float* m_cb  = (const float*)d_in[8];
    const float* m_lw  = (const float*)d_in[9];
    const float* m_lb  = (const float*)d_in[10];
    const float* f_emb = (const float*)d_in[11];
    const float* f_cw  = (const float*)d_in[12];
    const float* f_cb  = (const float*)d_in[13];
    const float* f_lw  = (const float*)d_in[14];
    const float* f_lb  = (const float*)d_in[15];
    const float* f_l2w = (const float*)d_in[16];
    const float* f_l2b = (const float*)d_in[17];
    float* out = (float*)d_out;

    cudaFuncSetAttribute(ggemm_e, cudaFuncAttributeMaxDynamicSharedMemorySize, SME_BYTES);

    // ---- enemy branch ----
    vmax_kernel      <<<256, 256>>>(e_emb);
    u_kernel         <<<384, dim3(128, 2)>>>(e_cw);
    convert_lw_kernel<<<16384, 256>>>(e_lw);
    ggemm_e          <<<128, 256, SME_BYTES>>>();
    lsum1_kernel     <<<256, 128>>>(e_lw, e_cb);
    lsum2_kernel     <<<1, 128>>>(e_lb);
    gather_e_kernel  <<<BB, 128>>>(x);

    // ---- manipulator -> tokens ----
    lmid_kernel      <<<64, 256>>>(m_lw);
    manip_kernel     <<<BB, 256>>>(m_cw, m_cb, m_lw, m_lb);

    // ---- friend branch ----
    vmax_kernel      <<<256, 256>>>(f_emb);
    u_kernel         <<<384, dim3(128, 2)>>>(f_cw);
    lwf2_kernel      <<<2048, 256>>>(f_lw, f_l2w);
    ggemm_f          <<<128, 128>>>();
    fc2a_kernel      <<<32, 128>>>(f_cb);
    fc2b_kernel      <<<1, 16>>>(f_lb, f_l2w, f_l2b);
    gather_f_kernel  <<<BB, 128>>>(out);
}

// round 7
// speedup vs baseline: 7.7219x; 1.3701x over previous
#include <cuda_runtime.h>
#include <math.h>
#include <stdint.h>

#define BB    256
#define KTOT  768        // 3 taps * 256 conv-out channels

// ---------------------------------------------------------------------------
// Static device scratch
// ---------------------------------------------------------------------------
__device__ __align__(128) float    g_VmaxT [512 * 128];     // enemy pairwise-max emb [c][p]
__device__ __align__(128) float    g_VmaxTf[512 * 128];     // friend
__device__ __align__(128) uint32_t g_U2Thi [KTOT * 128];    // enemy U tf32 hi
__device__ __align__(128) uint32_t g_U2Tlo [KTOT * 128];    // enemy U tf32 lo
__device__ __align__(128) uint32_t g_U2Tfhi[KTOT * 128];    // friend U tf32 hi
__device__ __align__(128) uint32_t g_lwEhi[32768 * 128];    // enemy lw tf32 hi
__device__ __align__(128) uint32_t g_lwElo[32768 * 128];    // tf32 lo
__device__ __align__(128) float    g_G [128 * 128 * 128];   // enemy table G[h][p][j]
__device__ __align__(128) float    g_Gf[128 * 128 * 16];    // friend table G[h][p][v]
__device__ __align__(128) float    g_lwF2[32768 * 16];      // friend lin1 @ lin2
__device__ __align__(128) float    g_tmp[256 * 128];
__device__ __align__(128) float    g_fconst[128];
__device__ __align__(128) float    g_tmpf[256 * 16];
__device__ __align__(128) float    g_fconst2[16];
__device__ __align__(128) float    g_Lmid[64 * 256];
__device__ __align__(128) float    g_Wsum[3 * 64 * 128];    // manip conv weight sums

// ---------------------------------------------------------------------------
// Helpers
// ---------------------------------------------------------------------------
__device__ __forceinline__ uint32_t f2tf32(float x) {
    uint32_t r;
    asm("cvt.rna.tf32.f32 %0, %1;" : "=r"(r) : "f"(x));
    return r;
}
__device__ __forceinline__ void mma8(float* c, const uint32_t* a, const uint32_t* b) {
    asm volatile(
        "mma.sync.aligned.m16n8k8.row.col.f32.tf32.tf32.f32 "
        "{%0,%1,%2,%3}, {%4,%5,%6,%7}, {%8,%9}, {%0,%1,%2,%3};"
        : "+f"(c[0]), "+f"(c[1]), "+f"(c[2]), "+f"(c[3])
        : "r"(a[0]), "r"(a[1]), "r"(a[2]), "r"(a[3]), "r"(b[0]), "r"(b[1]));
}
__device__ __forceinline__ void cp16(uint32_t saddr, const void* g) {
    asm volatile("cp.async.cg.shared.global [%0], [%1], 16;" :: "r"(saddr), "l"(g));
}
__device__ __forceinline__ void cp16z(uint32_t saddr, const void* g, int srcsz) {
    asm volatile("cp.async.cg.shared.global [%0], [%1], 16, %2;"
                 :: "r"(saddr), "l"(g), "r"(srcsz));
}
__device__ __forceinline__ void cp_commit() {
    asm volatile("cp.async.commit_group;");
}

// ---------------------------------------------------------------------------
// 1. vmax for both branches: blocks [0,256) enemy, [256,512) friend
// ---------------------------------------------------------------------------
__global__ void vmax_both(const float* __restrict__ e_emb, const float* __restrict__ f_emb)
{
    int bx = blockIdx.x;
    bool fr = bx >= 256;
    int idx = (fr ? bx - 256 : bx) * 256 + threadIdx.x;   // < 512*128
    int c = idx >> 7, p = idx & 127;
    const float* emb = fr ? f_emb : e_emb;
    float v = 0.0f;
    if (p < 105) {
        int a = 0, rem = p;
        while (rem >= 14 - a) { rem -= 14 - a; a++; }
        int b = a + rem;
        v = fmaxf(emb[a * 512 + c], emb[b * 512 + c]);
    }
    (fr ? g_VmaxTf : g_VmaxT)[idx] = v;
}

// ---------------------------------------------------------------------------
// 2. U for both branches: blocks [0,384) enemy (hi+lo), [384,768) friend (hi)
// ---------------------------------------------------------------------------
__global__ void u_both(const float* __restrict__ e_cw, const float* __restrict__ f_cw)
{
    __shared__ float Wcol[2][512];
    int bx = blockIdx.x;
    bool fr = bx >= 384;
    const float* cw   = fr ? f_cw : e_cw;
    const float* vmax = fr ? g_VmaxTf : g_VmaxT;
    int kbase = (fr ? bx - 384 : bx) * 2;

    int tx = threadIdx.x, ty = threadIdx.y;
    int tid = ty * 128 + tx;
    for (int i = tid; i < 1024; i += 256) {
        int yy = i >> 9, c = i & 511;
        int ky = kbase + yy;
        Wcol[yy][c] = cw[(ky & 255) * 4608 + c * 9 + (ky >> 8) * 3 + 1];
    }
    __syncthreads();
    float acc = 0.0f;
#pragma unroll 8
    for (int c = 0; c < 512; c++)
        acc += vmax[c * 128 + tx] * Wcol[ty][c];
    int addr = (kbase + ty) * 128 + tx;
    uint32_t hi = f2tf32(acc);
    if (fr) {
        g_U2Tfhi[addr] = hi;
    } else {
        g_U2Thi[addr] = hi;
        g_U2Tlo[addr] = f2tf32(acc - __uint_as_float(hi));
    }
}

// ---------------------------------------------------------------------------
// 3. convert enemy lw to tf32 hi/lo AND accumulate column sums (lsum1 fused).
//    One block per o; 256 threads = 2 rows (h) per step, 64 steps.
// ---------------------------------------------------------------------------
__global__ void convert_lsum(const float* __restrict__ lw, const float* __restrict__ cb)
{
    __shared__ float sred[256];
    int o = blockIdx.x, t = threadIdx.x;
    int j = t & 127, hoff = t >> 7;
    float sum = 0.0f;
    for (int h2 = 0; h2 < 64; h2++) {
        int h = h2 * 2 + hoff;
        size_t idx = (size_t)(o * 128 + h) * 128 + j;
        float v = lw[idx];
        uint32_t hi = f2tf32(v);
        g_lwEhi[idx] = hi;
        g_lwElo[idx] = f2tf32(v - __uint_as_float(hi));
        sum += v;
    }
    sred[t] = sum;
    __syncthreads();
    if (t < 128) g_tmp[o * 128 + t] = cb[o] * (sred[t] + sred[t + 128]);
}

__global__ void lsum2_kernel(const float* __restrict__ lb)
{
    int j = threadIdx.x;
    float s = lb[j];
    for (int o = 0; o < 256; o++) s += g_tmp[o * 128 + j];
    g_fconst[j] = s;
}

// ---------------------------------------------------------------------------
// 4. Enemy G-GEMM (3xTF32), 2-stage cp.async, N split across grid.y -> 2 blk/SM.
//    Block (hh, by): G[hh][p][by*64 + j], K=768.
// ---------------------------------------------------------------------------
#define ASTR 136
#define BSTR 72
#define AWORDS (16 * ASTR)           // 2176
#define BWORDS (16 * BSTR)           // 1152
#define AOFFALL (4 * AWORDS)
#define SME_BYTES ((4 * AWORDS + 4 * BWORDS) * 4)   // 53248

__global__ void __launch_bounds__(256, 2) ggemm_e()
{
    extern __shared__ uint32_t sm[];

    float acc[2][4][4];
#pragma unroll
    for (int i = 0; i < 2; i++)
#pragma unroll
        for (int j = 0; j < 4; j++)
#pragma unroll
            for (int q = 0; q < 4; q++) acc[i][j][q] = 0.0f;

    int t    = threadIdx.x;
    int lane = t & 31;
    int wid  = t >> 5;
    int wm   = wid & 3;
    int wn   = wid >> 2;           // 0..1, 32 cols each
    int gid  = lane >> 2;
    int tig  = lane & 3;
    int hh   = blockIdx.x;
    int by   = blockIdx.y;         // N half

    uint32_t sbase = (uint32_t)__cvta_generic_to_shared(sm);

    auto load_stage = [&](int s, int k0) {
        // A: 2 planes x 512 chunks, 2 chunks/thread/plane
#pragma unroll
        for (int pl = 0; pl < 2; pl++) {
#pragma unroll
            for (int q = 0; q < 2; q++) {
                int c   = t * 2 + q;
                int row = c >> 5;
                int c4  = (c & 31) * 4;
                uint32_t sa = sbase + (uint32_t)(((s * 2 + pl) * AWORDS + row * ASTR + c4) * 4);
                const uint32_t* g = (pl ? g_U2Tlo : g_U2Thi) + (size_t)(k0 + row) * 128 + c4;
                cp16(sa, g);
            }
        }
        // B: 2 planes x 256 chunks, 1 chunk/thread/plane (64 cols)
        {
            int row = t >> 4;
            int c4  = (t & 15) * 4;
            int k   = k0 + row;
            int tap = k >> 8, o = k & 255;
            int h   = hh + 1 - tap;
            int ok  = (h >= 0 && h < 128) ? 16 : 0;
            size_t off = ok ? ((size_t)(o * 128 + h) * 128 + by * 64 + c4) : 0;
#pragma unroll
            for (int pl = 0; pl < 2; pl++) {
                uint32_t sa = sbase + (uint32_t)((AOFFALL + (s * 2 + pl) * BWORDS + row * BSTR + c4) * 4);
                const uint32_t* g = (pl ? g_lwElo : g_lwEhi) + off;
                cp16z(sa, g, ok);
            }
        }
        cp_commit();
    };

    const int NIT = KTOT / 16;   // 48
    load_stage(0, 0);

    for (int it = 0; it < NIT; it++) {
        if (it + 1 < NIT) {
            load_stage((it + 1) & 1, (it + 1) * 16);
            asm volatile("cp.async.wait_group 1;");
        } else {
            asm volatile("cp.async.wait_group 0;");
        }
        __syncthreads();

        int s = it & 1;
        const uint32_t* A0 = sm + (s * 2 + 0) * AWORDS;
        const uint32_t* A1 = sm + (s * 2 + 1) * AWORDS;
        const uint32_t* B0 = sm + AOFFALL + (s * 2 + 0) * BWORDS;
        const uint32_t* B1 = sm + AOFFALL + (s * 2 + 1) * BWORDS;

#pragma unroll
        for (int ks = 0; ks < 2; ks++) {
            int kr = ks * 8;
            uint32_t af[2][2][4];
#pragma unroll
            for (int mi = 0; mi < 2; mi++) {
                int m = wm * 32 + mi * 16;
                af[0][mi][0] = A0[(kr + tig) * ASTR + m + gid];
                af[0][mi][1] = A0[(kr + tig) * ASTR + m + gid + 8];
                af[0][mi][2] = A0[(kr + tig + 4) * ASTR + m + gid];
                af[0][mi][3] = A0[(kr + tig + 4) * ASTR + m + gid + 8];
                af[1][mi][0] = A1[(kr + tig) * ASTR + m + gid];
                af[1][mi][1] = A1[(kr + tig) * ASTR + m + gid + 8];
                af[1][mi][2] = A1[(kr + tig + 4) * ASTR + m + gid];
                af[1][mi][3] = A1[(kr + tig + 4) * ASTR + m + gid + 8];
            }
#pragma unroll
            for (int nj = 0; nj < 4; nj++) {
                int n = wn * 32 + nj * 8;
                uint32_t bf[2][2];
                bf[0][0] = B0[(kr + tig) * BSTR + n + gid];
                bf[0][1] = B0[(kr + tig + 4) * BSTR + n + gid];
                bf[1][0] = B1[(kr + tig) * BSTR + n + gid];
                bf[1][1] = B1[(kr + tig + 4) * BSTR + n + gid];
#pragma unroll
                for (int mi = 0; mi < 2; mi++) {
                    mma8(acc[mi][nj], af[0][mi], bf[0]);
                    mma8(acc[mi][nj], af[0][mi], bf[1]);
                    mma8(acc[mi][nj], af[1][mi], bf[0]);
                }
            }
        }
        __syncthreads();
    }

    float* gbase = g_G + (size_t)hh * (128 * 128);
#pragma unroll
    for (int mi = 0; mi < 2; mi++) {
        int m = wm * 32 + mi * 16 + gid;
#pragma unroll
        for (int nj = 0; nj < 4; nj++) {
            int n = by * 64 + wn * 32 + nj * 8 + 2 * tig;
            gbase[(size_t)m * 128 + n]           = acc[mi][nj][0];
            gbase[(size_t)m * 128 + n + 1]       = acc[mi][nj][1];
            gbase[(size_t)(m + 8) * 128 + n]     = acc[mi][nj][2];
            gbase[(size_t)(m + 8) * 128 + n + 1] = acc[mi][nj][3];
        }
    }
}

// ---------------------------------------------------------------------------
// 5. Friend: lwF2[(o,h)][v] = sum_j lw1[(o,h)][j]*l2w[j][v]
// ---------------------------------------------------------------------------
__global__ void lwf2_kernel(const float* __restrict__ lw1, const float* __restrict__ l2w)
{
    __shared__ float lr[16][128];
    __shared__ float l2[128][16];
    int t = threadIdx.x, bx = blockIdx.x;
    for (int i = t; i < 2048; i += 256)
        lr[i >> 7][i & 127] = lw1[(size_t)bx * 2048 + i];
    for (int i = t; i < 2048; i += 256) {
        int j = i >> 4, v = i & 15;
        l2[j][v] = (v < 14) ? l2w[j * 14 + v] : 0.0f;
    }
    __syncthreads();
    int r = t >> 4, v = t & 15;
    float acc = 0.0f;
#pragma unroll 8
    for (int j = 0; j < 128; j++)
        acc += lr[r][j] * l2[j][v];
    g_lwF2[(size_t)(bx * 16 + r) * 16 + v] = acc;
}

// ---------------------------------------------------------------------------
// 6. Friend G-GEMM (single TF32), 2-stage cp.async
// ---------------------------------------------------------------------------
__global__ void __launch_bounds__(128) ggemm_f()
{
    __shared__ uint32_t Asm[2][16][136];
    __shared__ uint32_t Bsm[2][16][24];

    float acc[2][2][4];
#pragma unroll
    for (int i = 0; i < 2; i++)
#pragma unroll
        for (int j = 0; j < 2; j++)
#pragma unroll
            for (int q = 0; q < 4; q++) acc[i][j][q] = 0.0f;

    int t    = threadIdx.x;
    int lane = t & 31;
    int wm   = t >> 5;
    int gid  = lane >> 2;
    int tig  = lane & 3;
    int hh   = blockIdx.x;

    uint32_t saA = (uint32_t)__cvta_generic_to_shared(&Asm[0][0][0]);
    uint32_t saB = (uint32_t)__cvta_generic_to_shared(&Bsm[0][0][0]);

    auto load_stage = [&](int s, int k0) {
#pragma unroll
        for (int q = 0; q < 4; q++) {
            int c   = t * 4 + q;
            int row = c >> 5;
            int c4  = (c & 31) * 4;
            uint32_t sa = saA + (uint32_t)((s * 16 * 136 + row * 136 + c4) * 4);
            const uint32_t* g = g_U2Tfhi + (size_t)(k0 + row) * 128 + c4;
            cp16(sa, g);
        }
        if (t < 64) {
            int row = t >> 2;
            int c4  = (t & 3) * 4;
            int k   = k0 + row;
            int tap = k >> 8, o = k & 255;
            int h   = hh + 1 - tap;
            int ok  = (h >= 0 && h < 128) ? 16 : 0;
            size_t off = ok ? ((size_t)(o * 128 + h) * 16 + c4) : 0;
            uint32_t sa = saB + (uint32_t)((s * 16 * 24 + row * 24 + c4) * 4);
            cp16z(sa, (const uint32_t*)g_lwF2 + off, ok);
        }
        cp_commit();
    };

    const int NIT = KTOT / 16;
    load_stage(0, 0);

    for (int it = 0; it < NIT; it++) {
        if (it + 1 < NIT) {
            load_stage((it + 1) & 1, (it + 1) * 16);
            asm volatile("cp.async.wait_group 1;");
        } else {
            asm volatile("cp.async.wait_group 0;");
        }
        __syncthreads();
        int s = it & 1;

#pragma unroll
        for (int ks = 0; ks < 2; ks++) {
            int kr = ks * 8;
            uint32_t af[2][4];
#pragma unroll
            for (int mi = 0; mi < 2; mi++) {
                int m = wm * 32 + mi * 16;
                af[mi][0] = Asm[s][kr + tig][m + gid];
                af[mi][1] = Asm[s][kr + tig][m + gid + 8];
                af[mi][2] = Asm[s][kr + tig + 4][m + gid];
                af[mi][3] = Asm[s][kr + tig + 4][m + gid + 8];
            }
#pragma unroll
            for (int nj = 0; nj < 2; nj++) {
                int n = nj * 8;
                uint32_t bf[2];
                bf[0] = f2tf32(__uint_as_float(Bsm[s][kr + tig][n + gid]));
                bf[1] = f2tf32(__uint_as_float(Bsm[s][kr + tig + 4][n + gid]));
#pragma unroll
                for (int mi = 0; mi < 2; mi++)
                    mma8(acc[mi][nj], af[mi], bf);
            }
        }
        __syncthreads();
    }

    float* gbase = g_Gf + (size_t)hh * (128 * 16);
#pragma unroll
    for (int mi = 0; mi < 2; mi++) {
        int m = wm * 32 + mi * 16 + gid;
#pragma unroll
        for (int nj = 0; nj < 2; nj++) {
            int n = nj * 8 + 2 * tig;
            gbase[m * 16 + n]           = acc[mi][nj][0];
            gbase[m * 16 + n + 1]       = acc[mi][nj][1];
            gbase[(m + 8) * 16 + n]     = acc[mi][nj][2];
            gbase[(m + 8) * 16 + n + 1] = acc[mi][nj][3];
        }
    }
}

// ---------------------------------------------------------------------------
// 7. Friend bias constants
// ---------------------------------------------------------------------------
__global__ void fc2a_kernel(const float* __restrict__ cbf)
{
    int o = blockIdx.x * 8 + (threadIdx.x >> 4), v = threadIdx.x & 15;
    float acc = 0.0f;
    for (int h = 0; h < 128; h++)
        acc += g_lwF2[(size_t)(o * 128 + h) * 16 + v];
    g_tmpf[o * 16 + v] = cbf[o] * acc;
}
__global__ void fc2b_kernel(const float* __restrict__ lb1, const float* __restrict__ l2w,
                            const float* __restrict__ l2b)
{
    int v = threadIdx.x;   // 16
    float s = 0.0f;
    if (v < 14) {
        s = l2b[v];
        for (int j = 0; j < 128; j++) s += lb1[j] * l2w[j * 14 + v];
    }
    for (int o = 0; o < 256; o++) s += g_tmpf[o * 16 + v];
    g_fconst2[v] = (v < 14) ? s : 0.0f;
}

// ---------------------------------------------------------------------------
// 8. Prep: Lmid (idx<16384) + manip conv weight sums Wsum (next 24576)
// ---------------------------------------------------------------------------
__global__ void prep_misc(const float* __restrict__ mlw, const float* __restrict__ mcw)
{
    int idx = blockIdx.x * 256 + threadIdx.x;   // < 40960
    if (idx < 16384) {
        int o = idx >> 8, j = idx & 255;
        float s = 0.0f;
        for (int h = 1; h <= 126; h++)
            s += mlw[(size_t)(o * 128 + h) * 256 + j];
        g_Lmid[idx] = s;
    } else {
        int k = idx - 16384;                    // < 24576
        int row = k >> 7, i = k & 127;
        int g = row >> 6, o = row & 63;
        const float* wp = mcw + o * 1152 + i * 9;
        float w0 = wp[1], w1 = wp[4], w2 = wp[7];
        float ws = (g == 0) ? (w1 + w2) : ((g == 1) ? (w0 + w1 + w2) : (w0 + w1));
        g_Wsum[(g * 64 + o) * 128 + i] = ws;
    }
}

// ---------------------------------------------------------------------------
// 9. Fused per-batch chain: gather_e + softmax + manip + tokens + gather_f + out
// ---------------------------------------------------------------------------
__global__ void __launch_bounds__(256) fused_batch(const int* __restrict__ x,
                                                   const float* __restrict__ mcb,
                                                   const float* __restrict__ mlw,
                                                   const float* __restrict__ mlb,
                                                   float* __restrict__ out)
{
    __shared__ float eo[128];
    __shared__ float rr[192];
    __shared__ int   sp[128];
    __shared__ float red[128];
    __shared__ float part2[256];
    __shared__ int   tok[256];
    __shared__ float lg[16];
    int b = blockIdx.x, t = threadIdx.x;

    // ---- enemy pair indices ----
    if (t < 128) {
        int t0 = x[b * 256 + 2 * t], t1 = x[b * 256 + 2 * t + 1];
        int a = min(t0, t1), c = max(t0, t1);
        sp[t] = a * 14 + c - ((a * (a + 1)) >> 1);
    }
    __syncthreads();

    // ---- gather_e: 256 threads, each covers 64 h for its j ----
    {
        int j = t & 127, half = t >> 7;
        float ps = 0.0f;
        int h0 = half * 64;
#pragma unroll 4
        for (int i = 0; i < 64; i++) {
            int h = h0 + i;
            ps += g_G[(size_t)((h << 7) + sp[h]) * 128 + j];
        }
        part2[t] = ps;
    }
    __syncthreads();
    float fval = 0.0f;
    if (t < 128) { fval = g_fconst[t] + part2[t] + part2[t + 128]; red[t] = fval; }
    __syncthreads();
    for (int o = 64; o > 0; o >>= 1) { if (t < o) red[t] = fmaxf(red[t], red[t + o]); __syncthreads(); }
    float mx = red[0]; __syncthreads();
    float ev = 0.0f;
    if (t < 128) { ev = expf(fval - mx); red[t] = ev; }
    __syncthreads();
    for (int o = 64; o > 0; o >>= 1) { if (t < o) red[t] += red[t + o]; __syncthreads(); }
    if (t < 128) eo[t] = ev / red[0];
    __syncthreads();

    // ---- manip conv (3 h-groups x 64 o) ----
    if (t < 192) {
        int g = t / 64, o = t % 64;
        float acc = mcb[o];
        const float* wrow = g_Wsum + (g * 64 + o) * 128;
#pragma unroll 8
        for (int i = 0; i < 128; i++)
            acc += eo[i] * wrow[i];
        rr[t] = fmaxf(acc, 0.0f);
    }
    __syncthreads();

    // ---- manip linear + token quantization (all 256 t) ----
    {
        float mm = mlb[t];
        for (int o = 0; o < 64; o++) {
            mm += rr[o]       * mlw[(size_t)(o * 128) * 256 + t];
            mm += rr[64 + o]  * g_Lmid[o * 256 + t];
            mm += rr[128 + o] * mlw[(size_t)(o * 128 + 127) * 256 + t];
        }
        tok[t] = (int)(fmodf(floorf(fabsf(mm) * 100.0f), 14.0f));
    }
    __syncthreads();

    // ---- friend pair indices ----
    if (t < 128) {
        int t0 = tok[2 * t], t1 = tok[2 * t + 1];
        int a = min(t0, t1), c = max(t0, t1);
        sp[t] = a * 14 + c - ((a * (a + 1)) >> 1);
    }
    __syncthreads();

    // ---- gather_f (threads 0..127, hg groups of 16 h) ----
    if (t < 128) {
        int v = t & 15, hg = t >> 4;
        float ps = 0.0f;
#pragma unroll 4
        for (int i = 0; i < 16; i++) {
            int h = hg * 16 + i;
            ps += g_Gf[(size_t)((h << 7) + sp[h]) * 16 + v];
        }
        part2[t] = ps;
    }
    __syncthreads();
    if (t < 16) {
        float s = g_fconst2[t];
        for (int g = 0; g < 8; g++) s += part2[g * 16 + t];
        lg[t] = s;
    }
    __syncthreads();
    if (t == 0) {
        float mx2 = lg[0];
        for (int q = 1; q < 14; q++) mx2 = fmaxf(mx2, lg[q]);
        float sum = 0.0f;
        for (int q = 0; q < 14; q++) { float e2 = expf(lg[q] - mx2); lg[q] = e2; sum += e2; }
        float inv = 1.0f / sum;
        for (int q = 0; q < 14; q++) out[b * 14 + q] = lg[q] * inv;
    }
}

// ---------------------------------------------------------------------------
// Launch
// ---------------------------------------------------------------------------
extern "C" void kernel_launch(void* const* d_in, const int* in_sizes, int n_in,
                              void* d_out, int out_size)
{
    const int*   x     = (const int*)  d_in[0];
    const float* e_emb = (const float*)d_in[1];
    const float* e_cw  = (const float*)d_in[2];
    const float* e_cb  = (const float*)d_in[3];
    const float* e_lw  = (const float*)d_in[4];
    const float* e_lb  = (const float*)d_in[5];
    // d_in[6] = rand_proj (dead: fog_of_war is provably identity)
    const float* m_cw  = (const float*)d_in[7];
    const float* m_cb  = (const float*)d_in[8];
    const float* m_lw  = (const float*)d_in[9];
    const float* m_lb  = (const float*)d_in[10];
    const float* f_emb = (const float*)d_in[11];
    const float* f_cw  = (const float*)d_in[12];
    const float* f_cb  = (const float*)d_in[13];
    const float* f_lw  = (const float*)d_in[14];
    const float* f_lb  = (const float*)d_in[15];
    const float* f_l2w = (const float*)d_in[16];
    const float* f_l2b = (const float*)d_in[17];
    float* out = (float*)d_out;

    cudaFuncSetAttribute(ggemm_e, cudaFuncAttributeMaxDynamicSharedMemorySize, SME_BYTES);

    // ---- table building (both branches) ----
    vmax_both    <<<512, 256>>>(e_emb, f_emb);
    u_both       <<<768, dim3(128, 2)>>>(e_cw, f_cw);
    convert_lsum <<<256, 256>>>(e_lw, e_cb);
    lsum2_kernel <<<1, 128>>>(e_lb);
    ggemm_e      <<<dim3(128, 2), 256, SME_BYTES>>>();
    lwf2_kernel  <<<2048, 256>>>(f_lw, f_l2w);
    ggemm_f      <<<128, 128>>>();
    fc2a_kernel  <<<32, 128>>>(f_cb);
    fc2b_kernel  <<<1, 16>>>(f_lb, f_l2w, f_l2b);
    prep_misc    <<<160, 256>>>(m_lw, m_cw);

    // ---- per-batch fused chain ----
    fused_batch  <<<BB, 256>>>(x, m_cb, m_lw, m_lb, out);
}

// round 8
// speedup vs baseline: 11.2765x; 1.4603x over previous
#include <cuda_runtime.h>
#include <math.h>
#include <stdint.h>

#define BB    256
#define KTOT  768        // 3 taps * 256 conv-out channels

// ---------------------------------------------------------------------------
// Static device scratch
// ---------------------------------------------------------------------------
__device__ __align__(128) float    g_VmaxT [512 * 128];     // enemy pairwise-max emb [c][p]
__device__ __align__(128) float    g_VmaxTf[512 * 128];     // friend
__device__ __align__(128) uint32_t g_U2Thi [KTOT * 128];    // enemy U tf32 hi
__device__ __align__(128) uint32_t g_U2Tlo [KTOT * 128];    // enemy U tf32 lo
__device__ __align__(128) uint32_t g_U2Tfhi[KTOT * 128];    // friend U tf32 hi
__device__ __align__(128) float    g_G [128 * 128 * 128];   // enemy table G[h][p][j]
__device__ __align__(128) float    g_Gf[128 * 128 * 16];    // friend table G[h][p][v]
__device__ __align__(128) float    g_lwF2[32768 * 16];      // friend lin1 @ lin2
__device__ __align__(128) float    g_tmp[256 * 128];        // enemy cb[o]*colsum
__device__ __align__(128) float    g_Sf[256 * 128];         // friend lw1 h-colsums
__device__ __align__(128) float    g_fconst[128];
__device__ __align__(128) float    g_tmpf[256 * 16];
__device__ __align__(128) float    g_fconst2[16];
__device__ __align__(128) float    g_Lmid[64 * 256];
__device__ __align__(128) float    g_Wsum[3 * 64 * 128];    // manip conv weight sums

// ---------------------------------------------------------------------------
// Helpers
// ---------------------------------------------------------------------------
__device__ __forceinline__ uint32_t f2tf32(float x) {
    uint32_t r;
    asm("cvt.rna.tf32.f32 %0, %1;" : "=r"(r) : "f"(x));
    return r;
}
__device__ __forceinline__ void mma8(float* c, const uint32_t* a, const uint32_t* b) {
    asm volatile(
        "mma.sync.aligned.m16n8k8.row.col.f32.tf32.tf32.f32 "
        "{%0,%1,%2,%3}, {%4,%5,%6,%7}, {%8,%9}, {%0,%1,%2,%3};"
        : "+f"(c[0]), "+f"(c[1]), "+f"(c[2]), "+f"(c[3])
        : "r"(a[0]), "r"(a[1]), "r"(a[2]), "r"(a[3]), "r"(b[0]), "r"(b[1]));
}
__device__ __forceinline__ void cp16(uint32_t saddr, const void* g) {
    asm volatile("cp.async.cg.shared.global [%0], [%1], 16;" :: "r"(saddr), "l"(g));
}
__device__ __forceinline__ void cp16z(uint32_t saddr, const void* g, int srcsz) {
    asm volatile("cp.async.cg.shared.global [%0], [%1], 16, %2;"
                 :: "r"(saddr), "l"(g), "r"(srcsz));
}
__device__ __forceinline__ void cp_commit() {
    asm volatile("cp.async.commit_group;");
}

// ===========================================================================
// LAYER 1: vmax (e+f) | lw column-sums (e+f) | prep (Lmid + Wsum)
//   grid 1184 x 256
// ===========================================================================
__global__ void __launch_bounds__(256) stage1(
    const float* __restrict__ e_emb, const float* __restrict__ f_emb,
    const float* __restrict__ e_lw,  const float* __restrict__ e_cb,
    const float* __restrict__ f_lw,
    const float* __restrict__ mlw,   const float* __restrict__ mcw)
{
    __shared__ float sred[256];
    int bx = blockIdx.x, t = threadIdx.x;

    if (bx < 512) {                       // ---- vmax both ----
        bool fr = bx >= 256;
        int idx = (fr ? bx - 256 : bx) * 256 + t;
        int c = idx >> 7, p = idx & 127;
        const float* emb = fr ? f_emb : e_emb;
        float v = 0.0f;
        if (p < 105) {
            int a = 0, rem = p;
            while (rem >= 14 - a) { rem -= 14 - a; a++; }
            int b = a + rem;
            v = fmaxf(emb[a * 512 + c], emb[b * 512 + c]);
        }
        (fr ? g_VmaxTf : g_VmaxT)[idx] = v;
    } else if (bx < 1024) {               // ---- lw column sums (e / f) ----
        bool fr = bx >= 768;
        int o = fr ? bx - 768 : bx - 512;
        const float* lw = fr ? f_lw : e_lw;
        int j = t & 127, hoff = t >> 7;
        float sum = 0.0f;
        for (int h2 = 0; h2 < 64; h2++) {
            int h = h2 * 2 + hoff;
            sum += lw[(size_t)(o * 128 + h) * 128 + j];
        }
        sred[t] = sum;
        __syncthreads();
        if (t < 128) {
            float s = sred[t] + sred[t + 128];
            if (fr) g_Sf[o * 128 + t] = s;
            else    g_tmp[o * 128 + t] = e_cb[o] * s;
        }
    } else {                              // ---- prep: Lmid + Wsum ----
        int idx = (bx - 1024) * 256 + t;  // < 40960
        if (idx < 16384) {
            int o = idx >> 8, j = idx & 255;
            float s = 0.0f;
            for (int h = 1; h <= 126; h++)
                s += mlw[(size_t)(o * 128 + h) * 256 + j];
            g_Lmid[idx] = s;
        } else {
            int k = idx - 16384;          // < 24576
            int row = k >> 7, i = k & 127;
            int g = row >> 6, o = row & 63;
            const float* wp = mcw + o * 1152 + i * 9;
            float w0 = wp[1], w1 = wp[4], w2 = wp[7];
            float ws = (g == 0) ? (w1 + w2) : ((g == 1) ? (w0 + w1 + w2) : (w0 + w1));
            g_Wsum[(g * 64 + o) * 128 + i] = ws;
        }
    }
}

// ===========================================================================
// LAYER 2: u_both | lsum2 | lwf2 | fc2a
//   grid 2833 x 256
// ===========================================================================
__global__ void __launch_bounds__(256) stage2(
    const float* __restrict__ e_cw, const float* __restrict__ f_cw,
    const float* __restrict__ e_lb,
    const float* __restrict__ f_lw1, const float* __restrict__ f_l2w,
    const float* __restrict__ f_cb)
{
    __shared__ float Wcol[2][512];
    __shared__ float lr[16][128];
    __shared__ float l2[128][16];
    __shared__ float s2[256];
    int bx = blockIdx.x, t = threadIdx.x;

    if (bx < 768) {                       // ---- u for both branches ----
        bool fr = bx >= 384;
        const float* cw   = fr ? f_cw : e_cw;
        const float* vmax = fr ? g_VmaxTf : g_VmaxT;
        int kbase = (fr ? bx - 384 : bx) * 2;
        int tx = t & 127, ty = t >> 7;
        for (int i = t; i < 1024; i += 256) {
            int yy = i >> 9, c = i & 511;
            int ky = kbase + yy;
            Wcol[yy][c] = cw[(ky & 255) * 4608 + c * 9 + (ky >> 8) * 3 + 1];
        }
        __syncthreads();
        float acc = 0.0f;
#pragma unroll 8
        for (int c = 0; c < 512; c++)
            acc += vmax[c * 128 + tx] * Wcol[ty][c];
        int addr = (kbase + ty) * 128 + tx;
        uint32_t hi = f2tf32(acc);
        if (fr) {
            g_U2Tfhi[addr] = hi;
        } else {
            g_U2Thi[addr] = hi;
            g_U2Tlo[addr] = f2tf32(acc - __uint_as_float(hi));
        }
    } else if (bx == 768) {               // ---- lsum2 -> fconst ----
        int j = t & 127, half = t >> 7;
        float s = 0.0f;
        int o0 = half * 128;
        for (int o = o0; o < o0 + 128; o++) s += g_tmp[o * 128 + j];
        s2[t] = s;
        __syncthreads();
        if (t < 128) g_fconst[t] = e_lb[t] + s2[t] + s2[t + 128];
    } else if (bx < 2817) {               // ---- lwf2 ----
        int blk = bx - 769;
        for (int i = t; i < 2048; i += 256)
            lr[i >> 7][i & 127] = f_lw1[(size_t)blk * 2048 + i];
        for (int i = t; i < 2048; i += 256) {
            int j = i >> 4, v = i & 15;
            l2[j][v] = (v < 14) ? f_l2w[j * 14 + v] : 0.0f;
        }
        __syncthreads();
        int r = t >> 4, v = t & 15;
        float acc = 0.0f;
#pragma unroll 8
        for (int j = 0; j < 128; j++)
            acc += lr[r][j] * l2[j][v];
        g_lwF2[(size_t)(blk * 16 + r) * 16 + v] = acc;
    } else {                              // ---- fc2a from Sf ----
        int blk = bx - 2817;              // 0..15
        int o = blk * 16 + (t >> 4), v = t & 15;
        float acc = 0.0f;
        if (v < 14)
            for (int j = 0; j < 128; j++)
                acc += g_Sf[o * 128 + j] * f_l2w[j * 14 + v];
        g_tmpf[o * 16 + v] = f_cb[o] * acc;
    }
}

// ===========================================================================
// LAYER 3: ggemm_e (256 blk, first) | ggemm_f (128 blk) | fc2b (1 blk)
//   grid 385 x 256, dyn smem 44032 B
// ===========================================================================
#define ASTR 136
#define BSTR 72
#define AWORDS (16 * ASTR)               // 2176
#define BWORDS (16 * BSTR)               // 1152
#define AOFFALL (4 * AWORDS)             // 8704
#define SME_BYTES ((4 * AWORDS + 2 * BWORDS) * 4)   // 44032

__global__ void __launch_bounds__(256, 2) stage3(
    const float* __restrict__ e_lw,
    const float* __restrict__ f_lb, const float* __restrict__ f_l2w,
    const float* __restrict__ f_l2b)
{
    extern __shared__ uint32_t sm[];
    int bx = blockIdx.x, t = threadIdx.x;
    int lane = t & 31;
    int wid  = t >> 5;
    int gid  = lane >> 2;
    int tig  = lane & 3;
    uint32_t sbase = (uint32_t)__cvta_generic_to_shared(sm);

    if (bx < 256) {
        // ================= ggemm_e: 3xTF32, raw-B conversion =================
        int hh = bx >> 1, by = bx & 1;
        int wm = wid & 3, wn = wid >> 2;

        float acc[2][4][4];
#pragma unroll
        for (int i = 0; i < 2; i++)
#pragma unroll
            for (int j = 0; j < 4; j++)
#pragma unroll
                for (int q = 0; q < 4; q++) acc[i][j][q] = 0.0f;

        auto load_stage = [&](int s, int k0) {
            // A: 2 planes x 512 chunks (precomputed hi/lo)
#pragma unroll
            for (int pl = 0; pl < 2; pl++) {
#pragma unroll
                for (int q = 0; q < 2; q++) {
                    int c   = t * 2 + q;
                    int row = c >> 5;
                    int c4  = (c & 31) * 4;
                    uint32_t sa = sbase + (uint32_t)(((s * 2 + pl) * AWORDS + row * ASTR + c4) * 4);
                    const uint32_t* g = (pl ? g_U2Tlo : g_U2Thi) + (size_t)(k0 + row) * 128 + c4;
                    cp16(sa, g);
                }
            }
            // B: RAW lw row, 16 rows x 64 cols, 1 chunk per thread
            {
                int row = t >> 4;
                int c4  = (t & 15) * 4;
                int k   = k0 + row;
                int tap = k >> 8, o = k & 255;
                int h   = hh + 1 - tap;
                int ok  = (h >= 0 && h < 128) ? 16 : 0;
                const float* g = e_lw + (ok ? ((size_t)(o * 128 + h) * 128 + by * 64 + c4) : 0);
                uint32_t sa = sbase + (uint32_t)((AOFFALL + s * BWORDS + row * BSTR + c4) * 4);
                cp16z(sa, g, ok);
            }
            cp_commit();
        };

        const int NIT = KTOT / 16;   // 48
        load_stage(0, 0);

        for (int it = 0; it < NIT; it++) {
            if (it + 1 < NIT) {
                load_stage((it + 1) & 1, (it + 1) * 16);
                asm volatile("cp.async.wait_group 1;");
            } else {
                asm volatile("cp.async.wait_group 0;");
            }
            __syncthreads();

            int s = it & 1;
            const uint32_t* A0 = sm + (s * 2 + 0) * AWORDS;
            const uint32_t* A1 = sm + (s * 2 + 1) * AWORDS;
            const float*    Br = (const float*)(sm + AOFFALL + s * BWORDS);

#pragma unroll
            for (int ks = 0; ks < 2; ks++) {
                int kr = ks * 8;
                uint32_t af[2][2][4];
#pragma unroll
                for (int mi = 0; mi < 2; mi++) {
                    int m = wm * 32 + mi * 16;
                    af[0][mi][0] = A0[(kr + tig) * ASTR + m + gid];
                    af[0][mi][1] = A0[(kr + tig) * ASTR + m + gid + 8];
                    af[0][mi][2] = A0[(kr + tig + 4) * ASTR + m + gid];
                    af[0][mi][3] = A0[(kr + tig + 4) * ASTR + m + gid + 8];
                    af[1][mi][0] = A1[(kr + tig) * ASTR + m + gid];
                    af[1][mi][1] = A1[(kr + tig) * ASTR + m + gid + 8];
                    af[1][mi][2] = A1[(kr + tig + 4) * ASTR + m + gid];
                    af[1][mi][3] = A1[(kr + tig + 4) * ASTR + m + gid + 8];
                }
#pragma unroll
                for (int nj = 0; nj < 4; nj++) {
                    int n = wn * 32 + nj * 8;
                    float v0 = Br[(kr + tig) * BSTR + n + gid];
                    float v1 = Br[(kr + tig + 4) * BSTR + n + gid];
                    uint32_t bh[2], bl[2];
                    bh[0] = f2tf32(v0); bl[0] = f2tf32(v0 - __uint_as_float(bh[0]));
                    bh[1] = f2tf32(v1); bl[1] = f2tf32(v1 - __uint_as_float(bh[1]));
#pragma unroll
                    for (int mi = 0; mi < 2; mi++) {
                        mma8(acc[mi][nj], af[0][mi], bh);
                        mma8(acc[mi][nj], af[0][mi], bl);
                        mma8(acc[mi][nj], af[1][mi], bh);
                    }
                }
            }
            __syncthreads();
        }

        float* gbase = g_G + (size_t)hh * (128 * 128);
#pragma unroll
        for (int mi = 0; mi < 2; mi++) {
            int m = wm * 32 + mi * 16 + gid;
#pragma unroll
            for (int nj = 0; nj < 4; nj++) {
                int n = by * 64 + wn * 32 + nj * 8 + 2 * tig;
                gbase[(size_t)m * 128 + n]           = acc[mi][nj][0];
                gbase[(size_t)m * 128 + n + 1]       = acc[mi][nj][1];
                gbase[(size_t)(m + 8) * 128 + n]     = acc[mi][nj][2];
                gbase[(size_t)(m + 8) * 128 + n + 1] = acc[mi][nj][3];
            }
        }
    } else if (bx < 384) {
        // ================= ggemm_f: 8 warps x 16 M-rows, single TF32 ==========
        int hh = bx - 256;
        int wm = wid;                     // 0..7

        float acc[2][4];
#pragma unroll
        for (int j = 0; j < 2; j++)
#pragma unroll
            for (int q = 0; q < 4; q++) acc[j][q] = 0.0f;

        const int FB = 4352;              // B offset in words (A: 2 stages x 2176)

        auto load_stage = [&](int s, int k0) {
#pragma unroll
            for (int q = 0; q < 2; q++) {
                int c   = t * 2 + q;
                int row = c >> 5;
                int c4  = (c & 31) * 4;
                uint32_t sa = sbase + (uint32_t)((s * 2176 + row * 136 + c4) * 4);
                const uint32_t* g = g_U2Tfhi + (size_t)(k0 + row) * 128 + c4;
                cp16(sa, g);
            }
            if (t < 64) {
                int row = t >> 2;
                int c4  = (t & 3) * 4;
                int k   = k0 + row;
                int tap = k >> 8, o = k & 255;
                int h   = hh + 1 - tap;
                int ok  = (h >= 0 && h < 128) ? 16 : 0;
                const float* g = g_lwF2 + (ok ? ((size_t)(o * 128 + h) * 16 + c4) : 0);
                uint32_t sa = sbase + (uint32_t)((FB + s * 384 + row * 24 + c4) * 4);
                cp16z(sa, g, ok);
            }
            cp_commit();
        };

        const int NIT = KTOT / 16;
        load_stage(0, 0);

        for (int it = 0; it < NIT; it++) {
            if (it + 1 < NIT) {
                load_stage((it + 1) & 1, (it + 1) * 16);
                asm volatile("cp.async.wait_group 1;");
            } else {
                asm volatile("cp.async.wait_group 0;");
            }
            __syncthreads();
            int s = it & 1;
            const uint32_t* A  = sm + s * 2176;
            const float*    Br = (const float*)(sm + FB + s * 384);

#pragma unroll
            for (int ks = 0; ks < 2; ks++) {
                int kr = ks * 8;
                uint32_t af[4];
                int m = wm * 16;
                af[0] = A[(kr + tig) * 136 + m + gid];
                af[1] = A[(kr + tig) * 136 + m + gid + 8];
                af[2] = A[(kr + tig + 4) * 136 + m + gid];
                af[3] = A[(kr + tig + 4) * 136 + m + gid + 8];
#pragma unroll
                for (int nj = 0; nj < 2; nj++) {
                    int n = nj * 8;
                    uint32_t bf[2];
                    bf[0] = f2tf32(Br[(kr + tig) * 24 + n + gid]);
                    bf[1] = f2tf32(Br[(kr + tig + 4) * 24 + n + gid]);
                    mma8(acc[nj], af, bf);
                }
            }
            __syncthreads();
        }

        float* gbase = g_Gf + (size_t)hh * (128 * 16);
        int m = wm * 16 + gid;
#pragma unroll
        for (int nj = 0; nj < 2; nj++) {
            int n = nj * 8 + 2 * tig;
            gbase[m * 16 + n]           = acc[nj][0];
            gbase[m * 16 + n + 1]       = acc[nj][1];
            gbase[(m + 8) * 16 + n]     = acc[nj][2];
            gbase[(m + 8) * 16 + n + 1] = acc[nj][3];
        }
    } else {
        // ================= fc2b =================
        if (t < 16) {
            int v = t;
            float s = 0.0f;
            if (v < 14) {
                s = f_l2b[v];
                for (int j = 0; j < 128; j++) s += f_lb[j] * f_l2w[j * 14 + v];
            }
            for (int o = 0; o < 256; o++) s += g_tmpf[o * 16 + v];
            g_fconst2[v] = (v < 14) ? s : 0.0f;
        }
    }
}

// ===========================================================================
// LAYER 4: fused per-batch chain (unchanged from R7 — proven)
// ===========================================================================
__global__ void __launch_bounds__(256) fused_batch(const int* __restrict__ x,
                                                   const float* __restrict__ mcb,
                                                   const float* __restrict__ mlw,
                                                   const float* __restrict__ mlb,
                                                   float* __restrict__ out)
{
    __shared__ float eo[128];
    __shared__ float rr[192];
    __shared__ int   sp[128];
    __shared__ float red[128];
    __shared__ float part2[256];
    __shared__ int   tok[256];
    __shared__ float lg[16];
    int b = blockIdx.x, t = threadIdx.x;

    if (t < 128) {
        int t0 = x[b * 256 + 2 * t], t1 = x[b * 256 + 2 * t + 1];
        int a = min(t0, t1), c = max(t0, t1);
        sp[t] = a * 14 + c - ((a * (a + 1)) >> 1);
    }
    __syncthreads();

    {
        int j = t & 127, half = t >> 7;
        float ps = 0.0f;
        int h0 = half * 64;
#pragma unroll 4
        for (int i = 0; i < 64; i++) {
            int h = h0 + i;
            ps += g_G[(size_t)((h << 7) + sp[h]) * 128 + j];
        }
        part2[t] = ps;
    }
    __syncthreads();
    float fval = 0.0f;
    if (t < 128) { fval = g_fconst[t] + part2[t] + part2[t + 128]; red[t] = fval; }
    __syncthreads();
    for (int o = 64; o > 0; o >>= 1) { if (t < o) red[t] = fmaxf(red[t], red[t + o]); __syncthreads(); }
    float mx = red[0]; __syncthreads();
    float ev = 0.0f;
    if (t < 128) { ev = expf(fval - mx); red[t] = ev; }
    __syncthreads();
    for (int o = 64; o > 0; o >>= 1) { if (t < o) red[t] += red[t + o]; __syncthreads(); }
    if (t < 128) eo[t] = ev / red[0];
    __syncthreads();

    if (t < 192) {
        int g = t / 64, o = t % 64;
        float acc = mcb[o];
        const float* wrow = g_Wsum + (g * 64 + o) * 128;
#pragma unroll 8
        for (int i = 0; i < 128; i++)
            acc += eo[i] * wrow[i];
        rr[t] = fmaxf(acc, 0.0f);
    }
    __syncthreads();

    {
        float mm = mlb[t];
        for (int o = 0; o < 64; o++) {
            mm += rr[o]       * mlw[(size_t)(o * 128) * 256 + t];
            mm += rr[64 + o]  * g_Lmid[o * 256 + t];
            mm += rr[128 + o] * mlw[(size_t)(o * 128 + 127) * 256 + t];
        }
        tok[t] = (int)(fmodf(floorf(fabsf(mm) * 100.0f), 14.0f));
    }
    __syncthreads();

    if (t < 128) {
        int t0 = tok[2 * t], t1 = tok[2 * t + 1];
        int a = min(t0, t1), c = max(t0, t1);
        sp[t] = a * 14 + c - ((a * (a + 1)) >> 1);
    }
    __syncthreads();

    if (t < 128) {
        int v = t & 15, hg = t >> 4;
        float ps = 0.0f;
#pragma unroll 4
        for (int i = 0; i < 16; i++) {
            int h = hg * 16 + i;
            ps += g_Gf[(size_t)((h << 7) + sp[h]) * 16 + v];
        }
        part2[t] = ps;
    }
    __syncthreads();
    if (t < 16) {
        float s = g_fconst2[t];
        for (int g = 0; g < 8; g++) s += part2[g * 16 + t];
        lg[t] = s;
    }
    __syncthreads();
    if (t == 0) {
        float mx2 = lg[0];
        for (int q = 1; q < 14; q++) mx2 = fmaxf(mx2, lg[q]);
        float sum = 0.0f;
        for (int q = 0; q < 14; q++) { float e2 = expf(lg[q] - mx2); lg[q] = e2; sum += e2; }
        float inv = 1.0f / sum;
        for (int q = 0; q < 14; q++) out[b * 14 + q] = lg[q] * inv;
    }
}

// ---------------------------------------------------------------------------
// Launch: 4 layered launches (intra-layer work is independent & concurrent)
// ---------------------------------------------------------------------------
extern "C" void kernel_launch(void* const* d_in, const int* in_sizes, int n_in,
                              void* d_out, int out_size)
{
    const int*   x     = (const int*)  d_in[0];
    const float* e_emb = (const float*)d_in[1];
    const float* e_cw  = (const float*)d_in[2];
    const float* e_cb  = (const float*)d_in[3];
    const float* e_lw  = (const float*)d_in[4];
    const float* e_lb  = (const float*)d_in[5];
    // d_in[6] = rand_proj (dead: fog_of_war is provably identity)
    const float* m_cw  = (const float*)d_in[7];
    const float* m_cb  = (const float*)d_in[8];
    const float* m_lw  = (const float*)d_in[9];
    const float* m_lb  = (const float*)d_in[10];
    const float* f_emb = (const float*)d_in[11];
    const float* f_cw  = (const float*)d_in[12];
    const float* f_cb  = (const float*)d_in[13];
    const float* f_lw  = (const float*)d_in[14];
    const float* f_lb  = (const float*)d_in[15];
    const float* f_l2w = (const float*)d_in[16];
    const float* f_l2b = (const float*)d_in[17];
    float* out = (float*)d_out;

    cudaFuncSetAttribute(stage3, cudaFuncAttributeMaxDynamicSharedMemorySize, SME_BYTES);

    stage1      <<<1184, 256>>>(e_emb, f_emb, e_lw, e_cb, f_lw, m_lw, m_cw);
    stage2      <<<2833, 256>>>(e_cw, f_cw, e_lb, f_lw, f_l2w, f_cb);
    stage3      <<<385, 256, SME_BYTES>>>(e_lw, f_lb, f_l2w, f_l2b);
    fused_batch <<<BB, 256>>>(x, m_cb, m_lw, m_lb, out);
}